// round 9
// baseline (speedup 1.0000x reference)
#include <cuda_runtime.h>
#include <cuda_fp16.h>
#include <math.h>

#define NN    50000
#define NE    800000
#define ETOT  850000     // NE + NN self loops
#define H1    10
#define C1    36
#define D1    360        // H1*C1
#define ALP   12         // padded stride for als1/ald1 rows
#define D2    128
#define NG    128
#define MM1B  3125       // mm1 blocks inside fused scatter_mm1

typedef unsigned long long u64;

__device__ __forceinline__ u64 pack2(float a, float b) {
    u64 r; asm("mov.b64 %0, {%1, %2};" : "=l"(r) : "f"(a), "f"(b)); return r;
}
__device__ __forceinline__ u64 ffma2(u64 a, u64 b, u64 c) {
    u64 d; asm("fma.rn.f32x2 %0, %1, %2, %3;" : "=l"(d) : "l"(a), "l"(b), "l"(c)); return d;
}
__device__ __forceinline__ float2 unpack2(u64 v) {
    float2 r; asm("mov.b64 {%0, %1}, %2;" : "=f"(r.x), "=f"(r.y) : "l"(v)); return r;
}
__device__ __forceinline__ u64 h2_to_f32x2(unsigned h2) {
    float2 f = __half22float2(*(__half2*)&h2);
    return pack2(f.x, f.y);
}

// ---------------- device scratch (zero-initialized at module load) ----------------
__device__ int   g_src[ETOT];
__device__ int   g_dst[ETOT];
__device__ int   g_deg[NN];        // zeroed at end of each call (pool_kernel)
__device__ int   g_rowstart[NN];   // becomes row_end after scatter
__device__ int   g_inc[64];
__device__ int   g_flag[64];
__device__ int   g_ssrc[ETOT];     // src ids in CSR-by-dst order
__device__ float g_va[720];        // folded attention projections [sd][k][h]

__device__ __half g_h1h[(size_t)NN * D1];   // 36 MB (fp16 h1pre)
__device__ float g_als1[NN * ALP];
__device__ float g_ald1[NN * ALP];
__device__ float g_h1act[(size_t)NN * D1];  // 72 MB
__device__ __half g_h2h[(size_t)NN * D2];   // 12.8 MB (fp16 h2pre)
__device__ float g_als2[NN];
__device__ float g_ald2[NN];
__device__ float g_h2act[(size_t)NN * D2];  // 25.6 MB
__device__ float g_pool[NG * D2];           // 0-init semantics (values >= 0)

// ---------------- convert edges + va precompute (block 0) ----------------
__global__ void convert_kernel(const int* __restrict__ ei,
                               const float* __restrict__ W1,
                               const float* __restrict__ as1,
                               const float* __restrict__ ad1) {
    if (blockIdx.x == 0) {
        for (int idx = threadIdx.x; idx < 720; idx += 256) {
            int sd = idx / 360, r = idx % 360;
            int k = r / 10, h = r % 10;
            const float* a = sd ? ad1 : as1;
            float s = 0.f;
            for (int c = 0; c < C1; c++)
                s = fmaf(W1[k * D1 + h * C1 + c], a[h * C1 + c], s);
            g_va[sd * 360 + k * 10 + h] = s;
        }
    }
    int i = blockIdx.x * blockDim.x + threadIdx.x;
    if (i >= ETOT) return;
    int s, d;
    if (i < NE) {
        s = ei[i]; d = ei[NE + i];
        s = min(max(s, 0), NN - 1);
        d = min(max(d, 0), NN - 1);
    } else {
        s = d = i - NE;                      // self loop
    }
    g_src[i] = s; g_dst[i] = d;
    atomicAdd(&g_deg[d], 1);
}

// ---------------- exclusive scan (49 blocks, chained carry) ----------------
__global__ void scan_kernel() {
    __shared__ int tmp[1024];
    __shared__ int carry_s;
    int b = blockIdx.x, t = threadIdx.x;
    int i = b * 1024 + t;
    int v = (i < NN) ? g_deg[i] : 0;
    tmp[t] = v;
    __syncthreads();
    for (int off = 1; off < 1024; off <<= 1) {
        int add = (t >= off) ? tmp[t - off] : 0;
        __syncthreads();
        tmp[t] += add;
        __syncthreads();
    }
    if (t == 0) {
        int total = tmp[1023];
        int carry = 0;
        if (b > 0) {
            while (atomicAdd(&g_flag[b - 1], 0) == 0) { }
            carry = atomicAdd(&g_inc[b - 1], 0);
        }
        g_inc[b] = carry + total;
        __threadfence();
        atomicExch(&g_flag[b], 1);
        carry_s = carry;
    }
    __syncthreads();
    if (i < NN) g_rowstart[i] = carry_s + tmp[t] - v;   // exclusive global
}

// ---------------- fused scatter + mm1 (independent work, one launch) ---------------
// blocks [0, MM1B): mm1 GEMM  [h1h | als | ald] = x @ [W1 | va], 16 nodes/block
// blocks [MM1B, ..): scatter (rowstart doubles as cursor -> becomes row_end)
__global__ void scatter_mm1_kernel(const float* __restrict__ x,
                                   const float* __restrict__ W1) {
    int t = threadIdx.x;
    if (blockIdx.x >= MM1B) {
        int i = (blockIdx.x - MM1B) * 384 + t;
        if (i < ETOT) {
            int d = g_dst[i];
            int pos = atomicAdd(&g_rowstart[d], 1);
            g_ssrc[pos] = g_src[i];
        }
        return;
    }
    int n0 = blockIdx.x * 16;
    __shared__ u64 xsp[C1 * 8];   // [k][pair m]
    if (t < 288) {
        int k = t >> 3, m = t & 7;
        float a = x[(size_t)(n0 + 2 * m) * C1 + k];
        float b = x[(size_t)(n0 + 2 * m + 1) * C1 + k];
        xsp[k * 8 + m] = pack2(a, b);
    }
    __syncthreads();
    const float* wptr; int wstride;
    if (t < D1)            { wptr = W1 + t; wstride = D1; }
    else if (t < D1 + 20)  { int j = t - D1; wptr = g_va + (j & 1) * 360 + (j >> 1); wstride = 10; }
    else                   { wptr = W1 + t - 24; wstride = D1; }   // idle lanes, harmless
    u64 acc[8] = {0, 0, 0, 0, 0, 0, 0, 0};
    for (int k = 0; k < C1; k++) {
        float w = wptr[k * wstride];
        u64 ww = pack2(w, w);
        const ulonglong2* row = (const ulonglong2*)(xsp + k * 8);
#pragma unroll
        for (int q = 0; q < 4; q++) {
            ulonglong2 v = row[q];
            acc[2 * q]     = ffma2(v.x, ww, acc[2 * q]);
            acc[2 * q + 1] = ffma2(v.y, ww, acc[2 * q + 1]);
        }
    }
    if (t < D1) {
#pragma unroll
        for (int m = 0; m < 8; m++) {
            float2 v = unpack2(acc[m]);
            g_h1h[(size_t)(n0 + 2 * m) * D1 + t]     = __float2half(v.x);
            g_h1h[(size_t)(n0 + 2 * m + 1) * D1 + t] = __float2half(v.y);
        }
    } else if (t < D1 + 20) {
        int j = t - D1, h = j >> 1;
        float* dst = (j & 1) ? g_ald1 : g_als1;
#pragma unroll
        for (int m = 0; m < 8; m++) {
            float2 v = unpack2(acc[m]);
            dst[(n0 + 2 * m) * ALP + h]     = v.x;
            dst[(n0 + 2 * m + 1) * ALP + h] = v.y;
        }
    }
}

// ---------------- layer-1 aggregation with inline softmax (fp16 gather) -----------
__global__ void agg1_kernel(const float* __restrict__ b1) {
    int node = blockIdx.x;
    int t = threadIdx.x;            // 128
    __shared__ int   ssrcs[128];
    __shared__ float sp[128 * H1];  // 5 KB
    __shared__ float aldn[H1];
    __shared__ float ssum[H1];
    if (t < H1) aldn[t] = g_ald1[node * ALP + t];

    int deg = g_deg[node];
    int start = g_rowstart[node] - deg;   // rowstart holds row_end post-scatter
    const int head = (t < 90) ? (t / 9) : 0;
    u64 acc01 = 0, acc23 = 0;
    float hsum = 0.f;

    for (int base = 0; base < deg; base += 128) {
        int m = min(128, deg - base);
        __syncthreads();
        if (t < m) {
            int s = g_ssrc[start + base + t];
            ssrcs[t] = s;
            const float* ar = &g_als1[(size_t)s * ALP];
            float4 a0 = *(const float4*)ar;
            float4 a1 = *(const float4*)(ar + 4);
            float2 a2 = *(const float2*)(ar + 8);
            float e;
#define DOH(val, h) e = (val) + aldn[h]; e = (e > 0.f) ? e : 0.2f * e; sp[t * H1 + (h)] = __expf(e);
            DOH(a0.x, 0) DOH(a0.y, 1) DOH(a0.z, 2) DOH(a0.w, 3)
            DOH(a1.x, 4) DOH(a1.y, 5) DOH(a1.z, 6) DOH(a1.w, 7)
            DOH(a2.x, 8) DOH(a2.y, 9)
#undef DOH
        }
        __syncthreads();
        if (t < 90) {
            const char* hb = (const char*)g_h1h + 8 * t;  // features 4t..4t+3
            int e = 0;
            for (; e + 2 <= m; e += 2) {
                int s0 = ssrcs[e], s1 = ssrcs[e + 1];
                float p0 = sp[e * H1 + head];
                float p1 = sp[(e + 1) * H1 + head];
                u64 w0 = *(const u64*)(hb + (size_t)s0 * (D1 * 2));
                u64 w1 = *(const u64*)(hb + (size_t)s1 * (D1 * 2));
                u64 q0 = pack2(p0, p0), q1 = pack2(p1, p1);
                acc01 = ffma2(h2_to_f32x2((unsigned)w0),         q0, acc01);
                acc23 = ffma2(h2_to_f32x2((unsigned)(w0 >> 32)), q0, acc23);
                acc01 = ffma2(h2_to_f32x2((unsigned)w1),         q1, acc01);
                acc23 = ffma2(h2_to_f32x2((unsigned)(w1 >> 32)), q1, acc23);
            }
            if (e < m) {
                int s0 = ssrcs[e];
                float p0 = sp[e * H1 + head];
                u64 w0 = *(const u64*)(hb + (size_t)s0 * (D1 * 2));
                u64 q0 = pack2(p0, p0);
                acc01 = ffma2(h2_to_f32x2((unsigned)w0),         q0, acc01);
                acc23 = ffma2(h2_to_f32x2((unsigned)(w0 >> 32)), q0, acc23);
            }
        } else if (t >= 90 && t < 100) {
            int h = t - 90;
            for (int e = 0; e < m; e++) hsum += sp[e * H1 + h];
        }
    }
    if (t >= 90 && t < 100) ssum[t - 90] = hsum;
    __syncthreads();
    if (t < 90) {
        float rs = 1.0f / (ssum[head] + 1e-16f);
        float2 v01 = unpack2(acc01);
        float2 v23 = unpack2(acc23);
        float4 bv = *(const float4*)(b1 + 4 * t);
        float4 o;
        o.x = v01.x * rs + bv.x;
        o.y = v01.y * rs + bv.y;
        o.z = v23.x * rs + bv.z;
        o.w = v23.y * rs + bv.w;
        o.x = (o.x > 0.f) ? o.x : (__expf(o.x) - 1.f);
        o.y = (o.y > 0.f) ? o.y : (__expf(o.y) - 1.f);
        o.z = (o.z > 0.f) ? o.z : (__expf(o.z) - 1.f);
        o.w = (o.w > 0.f) ? o.w : (__expf(o.w) - 1.f);
        *(float4*)(g_h1act + (size_t)node * D1 + 4 * t) = o;
    }
}

// ---------------- layer 2 GEMM + fused al2 (fp16 h2pre out) ----------------
#define MM2_N 32
#define MM2_STRIDE 36
#define YS_STRIDE 132
__global__ void mm2_kernel(const float* __restrict__ W2,
                           const float* __restrict__ asrc2,
                           const float* __restrict__ adst2) {
    extern __shared__ float smem_[];
    float* xs = smem_;                          // [D1][36]
    float* ys = smem_ + D1 * MM2_STRIDE;        // [32][132]
    int n0 = blockIdx.x * MM2_N;
    int t = threadIdx.x;                        // 128
    for (int i = t; i < MM2_N * D1; i += 128) {
        int n = i / D1, k = i % D1;
        float v = (n0 + n < NN) ? g_h1act[(size_t)(n0 + n) * D1 + k] : 0.f;
        xs[k * MM2_STRIDE + n] = v;
    }
    __syncthreads();
    u64 acc[MM2_N / 2];
#pragma unroll
    for (int p = 0; p < MM2_N / 2; p++) acc[p] = 0;
    for (int k = 0; k < D1; k++) {
        float w = W2[k * D2 + t];
        u64 wf2 = pack2(w, w);
        const ulonglong2* row = (const ulonglong2*)(xs + k * MM2_STRIDE);
#pragma unroll
        for (int q = 0; q < MM2_N / 4; q++) {
            ulonglong2 v = row[q];
            acc[2 * q]     = ffma2(v.x, wf2, acc[2 * q]);
            acc[2 * q + 1] = ffma2(v.y, wf2, acc[2 * q + 1]);
        }
    }
#pragma unroll
    for (int p = 0; p < MM2_N / 2; p++) {
        float2 a = unpack2(acc[p]);
        int n = n0 + 2 * p;
        if (n < NN)     g_h2h[(size_t)n * D2 + t] = __float2half(a.x);
        if (n + 1 < NN) g_h2h[(size_t)(n + 1) * D2 + t] = __float2half(a.y);
        ys[(2 * p) * YS_STRIDE + t]     = a.x;
        ys[(2 * p + 1) * YS_STRIDE + t] = a.y;
    }
    __syncthreads();
    {
        int n = t >> 2, c0 = (t & 3) * 32;
        float ss = 0.f, sd = 0.f;
        const float* yr = ys + n * YS_STRIDE;
        for (int k = c0; k < c0 + 32; k++) {
            float v = yr[k];
            ss = fmaf(v, asrc2[k], ss);
            sd = fmaf(v, adst2[k], sd);
        }
        ss += __shfl_xor_sync(0xffffffffu, ss, 1);
        ss += __shfl_xor_sync(0xffffffffu, ss, 2);
        sd += __shfl_xor_sync(0xffffffffu, sd, 1);
        sd += __shfl_xor_sync(0xffffffffu, sd, 2);
        if ((t & 3) == 0 && n0 + n < NN) {
            g_als2[n0 + n] = ss;
            g_ald2[n0 + n] = sd;
        }
    }
}

// ---------------- layer-2 aggregation: warp per node (fp16 gather) ----------------
__global__ void agg2_kernel(const float* __restrict__ b2) {
    int node = blockIdx.x * 4 + (threadIdx.x >> 5);
    int lane = threadIdx.x & 31;
    float aldn = g_ald2[node];
    int deg = g_deg[node];
    int start = g_rowstart[node] - deg;
    u64 acc01 = 0, acc23 = 0;
    float psum = 0.f;
    const char* hb = (const char*)g_h2h + 8 * lane;   // features 4*lane..4*lane+3
    for (int base = 0; base < deg; base += 32) {
        int m = min(32, deg - base);
        int s = 0; float p = 0.f;
        if (lane < m) {
            s = g_ssrc[start + base + lane];
            float e = g_als2[s] + aldn;
            e = (e > 0.f) ? e : 0.2f * e;
            p = __expf(e);
        }
        psum += p;
        int j = 0;
        for (; j + 2 <= m; j += 2) {
            int   s0 = __shfl_sync(0xffffffffu, s, j);
            float p0 = __shfl_sync(0xffffffffu, p, j);
            int   s1 = __shfl_sync(0xffffffffu, s, j + 1);
            float p1 = __shfl_sync(0xffffffffu, p, j + 1);
            u64 w0 = *(const u64*)(hb + (size_t)s0 * (D2 * 2));
            u64 w1 = *(const u64*)(hb + (size_t)s1 * (D2 * 2));
            u64 q0 = pack2(p0, p0), q1 = pack2(p1, p1);
            acc01 = ffma2(h2_to_f32x2((unsigned)w0),         q0, acc01);
            acc23 = ffma2(h2_to_f32x2((unsigned)(w0 >> 32)), q0, acc23);
            acc01 = ffma2(h2_to_f32x2((unsigned)w1),         q1, acc01);
            acc23 = ffma2(h2_to_f32x2((unsigned)(w1 >> 32)), q1, acc23);
        }
        if (j < m) {
            int   s0 = __shfl_sync(0xffffffffu, s, j);
            float p0 = __shfl_sync(0xffffffffu, p, j);
            u64 w0 = *(const u64*)(hb + (size_t)s0 * (D2 * 2));
            u64 q0 = pack2(p0, p0);
            acc01 = ffma2(h2_to_f32x2((unsigned)w0),         q0, acc01);
            acc23 = ffma2(h2_to_f32x2((unsigned)(w0 >> 32)), q0, acc23);
        }
    }
#pragma unroll
    for (int off = 16; off; off >>= 1)
        psum += __shfl_xor_sync(0xffffffffu, psum, off);
    float rs = 1.0f / (psum + 1e-16f);
    float2 v01 = unpack2(acc01);
    float2 v23 = unpack2(acc23);
    float4 bv = *(const float4*)(b2 + 4 * lane);
    float4 o;
    o.x = fmaxf(v01.x * rs + bv.x, 0.f);
    o.y = fmaxf(v01.y * rs + bv.y, 0.f);
    o.z = fmaxf(v23.x * rs + bv.z, 0.f);
    o.w = fmaxf(v23.y * rs + bv.w, 0.f);
    *(float4*)(g_h2act + (size_t)node * D2 + 4 * lane) = o;
}

// ---------------- pool (sorted batch) + end-of-call cleanup ----------------
__global__ void pool_kernel(const int* __restrict__ batch) {
    int t = threadIdx.x;                   // 128 = feature
    int n0 = blockIdx.x * 128;
    int n1 = min(n0 + 128, NN);
    float cur = 0.f;                       // values >= 0 (post-relu)
    int curb = min(max(batch[n0], 0), NG - 1);
    for (int n = n0; n < n1; n++) {
        int b = min(max(batch[n], 0), NG - 1);
        if (b != curb) {
            atomicMax((int*)&g_pool[curb * D2 + t], __float_as_int(cur));
            cur = 0.f;
            curb = b;
        }
        cur = fmaxf(cur, g_h2act[(size_t)n * D2 + t]);
    }
    atomicMax((int*)&g_pool[curb * D2 + t], __float_as_int(cur));
    // cleanup for next call (deg no longer read this call)
    for (int n = n0 + t; n < n1; n += 128) g_deg[n] = 0;
    if (blockIdx.x == 0 && t < 64) {
        g_flag[t] = 0; g_inc[t] = 0;
    }
}

__global__ void fc_kernel(const float* __restrict__ fcw,
                          const float* __restrict__ fcb,
                          float* __restrict__ out) {
    int gi = blockIdx.x, t = threadIdx.x;
    __shared__ float gs[D2];
    float gv = g_pool[gi * D2 + t];
    if (!(gv >= 0.f)) gv = 0.f;
    gs[t] = gv;
    __syncthreads();
    float s = 0.f;
    for (int k = 0; k < D2; k++)
        s = fmaf(gs[k], fcw[k * D2 + t], s);
    out[gi * D2 + t] = fmaxf(s + fcb[t], 0.f);
}

// ---------------- launcher ----------------
extern "C" void kernel_launch(void* const* d_in, const int* in_sizes, int n_in,
                              void* d_out, int out_size) {
    const float* x     = (const float*)d_in[0];
    const int*   ei    = (const int*)d_in[1];
    const int*   batch = (const int*)d_in[2];
    const float* W1    = (const float*)d_in[3];
    const float* as1   = (const float*)d_in[4];
    const float* ad1   = (const float*)d_in[5];
    const float* b1    = (const float*)d_in[6];
    const float* W2    = (const float*)d_in[7];
    const float* as2   = (const float*)d_in[8];
    const float* ad2   = (const float*)d_in[9];
    const float* b2    = (const float*)d_in[10];
    const float* fcw   = (const float*)d_in[11];
    const float* fcb   = (const float*)d_in[12];
    float* out = (float*)d_out;

    const int mm2_smem = (D1 * MM2_STRIDE + MM2_N * YS_STRIDE) * 4;
    static bool attr_set = false;
    if (!attr_set) {
        cudaFuncSetAttribute(mm2_kernel,
                             cudaFuncAttributeMaxDynamicSharedMemorySize,
                             mm2_smem);
        attr_set = true;
    }

    const int scat_blocks = (ETOT + 383) / 384;
    convert_kernel<<<(ETOT + 255) / 256, 256>>>(ei, W1, as1, ad1);  // idx 0
    scan_kernel<<<49, 1024>>>();                                    // idx 1
    scatter_mm1_kernel<<<MM1B + scat_blocks, 384>>>(x, W1);         // idx 2
    agg1_kernel<<<NN, 128>>>(b1);                                   // idx 3 (profiled)

    mm2_kernel<<<(NN + MM2_N - 1) / MM2_N, 128, mm2_smem>>>(W2, as2, ad2);
    agg2_kernel<<<NN / 4, 128>>>(b2);

    pool_kernel<<<(NN + 127) / 128, 128>>>(batch);
    fc_kernel<<<NG, D2>>>(fcw, fcb, out);
}

// round 10
// speedup vs baseline: 1.0227x; 1.0227x over previous
#include <cuda_runtime.h>
#include <cuda_fp16.h>
#include <math.h>

#define NN    50000
#define NE    800000
#define ETOT  850000     // NE + NN self loops
#define H1    10
#define C1    36
#define D1    360        // H1*C1
#define ALP   12         // padded stride for als1/ald1 rows
#define D2    128
#define NG    128

typedef unsigned long long u64;

__device__ __forceinline__ u64 pack2(float a, float b) {
    u64 r; asm("mov.b64 %0, {%1, %2};" : "=l"(r) : "f"(a), "f"(b)); return r;
}
__device__ __forceinline__ u64 ffma2(u64 a, u64 b, u64 c) {
    u64 d; asm("fma.rn.f32x2 %0, %1, %2, %3;" : "=l"(d) : "l"(a), "l"(b), "l"(c)); return d;
}
__device__ __forceinline__ float2 unpack2(u64 v) {
    float2 r; asm("mov.b64 {%0, %1}, %2;" : "=f"(r.x), "=f"(r.y) : "l"(v)); return r;
}
__device__ __forceinline__ u64 h2_to_f32x2(unsigned h2) {
    float2 f = __half22float2(*(__half2*)&h2);
    return pack2(f.x, f.y);
}

// ---------------- device scratch (zero-initialized at module load) ----------------
__device__ int   g_src[ETOT];
__device__ int   g_dst[ETOT];
__device__ int   g_deg[NN];        // zeroed at end of each call (pool_kernel)
__device__ int   g_rowstart[NN];   // becomes row_end after scatter
__device__ int   g_inc[64];
__device__ int   g_flag[64];
__device__ int   g_ssrc[ETOT];     // src ids in CSR-by-dst order
__device__ float g_va[720];        // folded attention projections [sd][k][h]

__device__ __half g_h1h[(size_t)NN * D1];   // 36 MB (fp16 h1pre)
__device__ float g_als1[NN * ALP];
__device__ float g_ald1[NN * ALP];
__device__ float g_h1act[(size_t)NN * D1];  // 72 MB
__device__ __half g_h2h[(size_t)NN * D2];   // 12.8 MB (fp16 h2pre)
__device__ float g_als2[NN];
__device__ float g_ald2[NN];
__device__ float g_h2act[(size_t)NN * D2];  // 25.6 MB
__device__ float g_pool[NG * D2];           // 0-init semantics (values >= 0)

// ---------------- convert edges + va precompute (block 0) ----------------
__global__ void convert_kernel(const int* __restrict__ ei,
                               const float* __restrict__ W1,
                               const float* __restrict__ as1,
                               const float* __restrict__ ad1) {
    if (blockIdx.x == 0) {
        for (int idx = threadIdx.x; idx < 720; idx += 256) {
            int sd = idx / 360, r = idx % 360;
            int k = r / 10, h = r % 10;
            const float* a = sd ? ad1 : as1;
            float s = 0.f;
            for (int c = 0; c < C1; c++)
                s = fmaf(W1[k * D1 + h * C1 + c], a[h * C1 + c], s);
            g_va[sd * 360 + k * 10 + h] = s;
        }
    }
    int i = blockIdx.x * blockDim.x + threadIdx.x;
    if (i >= ETOT) return;
    int s, d;
    if (i < NE) {
        s = ei[i]; d = ei[NE + i];
        s = min(max(s, 0), NN - 1);
        d = min(max(d, 0), NN - 1);
    } else {
        s = d = i - NE;                      // self loop
    }
    g_src[i] = s; g_dst[i] = d;
    atomicAdd(&g_deg[d], 1);
}

// ---------------- exclusive scan (49 blocks, chained carry) ----------------
__global__ void scan_kernel() {
    __shared__ int tmp[1024];
    __shared__ int carry_s;
    int b = blockIdx.x, t = threadIdx.x;
    int i = b * 1024 + t;
    int v = (i < NN) ? g_deg[i] : 0;
    tmp[t] = v;
    __syncthreads();
    for (int off = 1; off < 1024; off <<= 1) {
        int add = (t >= off) ? tmp[t - off] : 0;
        __syncthreads();
        tmp[t] += add;
        __syncthreads();
    }
    if (t == 0) {
        int total = tmp[1023];
        int carry = 0;
        if (b > 0) {
            while (atomicAdd(&g_flag[b - 1], 0) == 0) { }
            carry = atomicAdd(&g_inc[b - 1], 0);
        }
        g_inc[b] = carry + total;
        __threadfence();
        atomicExch(&g_flag[b], 1);
        carry_s = carry;
    }
    __syncthreads();
    if (i < NN) g_rowstart[i] = carry_s + tmp[t] - v;   // exclusive global
}

// ---------------- scatter (rowstart doubles as cursor -> becomes row_end) ---------
__global__ void scatter_kernel() {
    int i = blockIdx.x * blockDim.x + threadIdx.x;
    if (i >= ETOT) return;
    int d = g_dst[i];
    int pos = atomicAdd(&g_rowstart[d], 1);
    g_ssrc[pos] = g_src[i];
}

// ---------------- layer 1 GEMM: [h1h | als | ald] = x @ [W1 | va] ----------------
__global__ void mm1_kernel(const float* __restrict__ x,
                           const float* __restrict__ W1) {
    // 16 nodes per block, 384 threads (one output column each; 360 feat + 20 attn)
    int n0 = blockIdx.x * 16;
    int t = threadIdx.x;
    __shared__ u64 xsp[C1 * 8];   // [k][pair m]
    if (t < 288) {
        int k = t >> 3, m = t & 7;
        float a = x[(size_t)(n0 + 2 * m) * C1 + k];
        float b = x[(size_t)(n0 + 2 * m + 1) * C1 + k];
        xsp[k * 8 + m] = pack2(a, b);
    }
    __syncthreads();
    const float* wptr; int wstride;
    if (t < D1)            { wptr = W1 + t; wstride = D1; }
    else if (t < D1 + 20)  { int j = t - D1; wptr = g_va + (j & 1) * 360 + (j >> 1); wstride = 10; }
    else                   { wptr = W1 + t - 24; wstride = D1; }   // idle lanes, harmless
    u64 acc[8] = {0, 0, 0, 0, 0, 0, 0, 0};
    for (int k = 0; k < C1; k++) {
        float w = wptr[k * wstride];
        u64 ww = pack2(w, w);
        const ulonglong2* row = (const ulonglong2*)(xsp + k * 8);
#pragma unroll
        for (int q = 0; q < 4; q++) {
            ulonglong2 v = row[q];
            acc[2 * q]     = ffma2(v.x, ww, acc[2 * q]);
            acc[2 * q + 1] = ffma2(v.y, ww, acc[2 * q + 1]);
        }
    }
    if (t < D1) {
#pragma unroll
        for (int m = 0; m < 8; m++) {
            float2 v = unpack2(acc[m]);
            g_h1h[(size_t)(n0 + 2 * m) * D1 + t]     = __float2half(v.x);
            g_h1h[(size_t)(n0 + 2 * m + 1) * D1 + t] = __float2half(v.y);
        }
    } else if (t < D1 + 20) {
        int j = t - D1, h = j >> 1;
        float* dst = (j & 1) ? g_ald1 : g_als1;
#pragma unroll
        for (int m = 0; m < 8; m++) {
            float2 v = unpack2(acc[m]);
            dst[(n0 + 2 * m) * ALP + h]     = v.x;
            dst[(n0 + 2 * m + 1) * ALP + h] = v.y;
        }
    }
}

// ---------------- layer-1 aggregation with inline softmax (fp16 gather, MLP=4) ----
__global__ void agg1_kernel(const float* __restrict__ b1) {
    int node = blockIdx.x;
    int t = threadIdx.x;            // 128
    __shared__ int   ssrcs[128];
    __shared__ float sp[128 * H1];  // 5 KB
    __shared__ float aldn[H1];
    __shared__ float ssum[H1];
    if (t < H1) aldn[t] = g_ald1[node * ALP + t];

    int deg = g_deg[node];
    int start = g_rowstart[node] - deg;   // rowstart holds row_end post-scatter
    const int head = (t < 90) ? (t / 9) : 0;
    u64 acc01 = 0, acc23 = 0;
    float hsum = 0.f;

    for (int base = 0; base < deg; base += 128) {
        int m = min(128, deg - base);
        __syncthreads();
        if (t < m) {
            int s = g_ssrc[start + base + t];
            ssrcs[t] = s;
            const float* ar = &g_als1[(size_t)s * ALP];
            float4 a0 = *(const float4*)ar;
            float4 a1 = *(const float4*)(ar + 4);
            float2 a2 = *(const float2*)(ar + 8);
            float e;
#define DOH(val, h) e = (val) + aldn[h]; e = (e > 0.f) ? e : 0.2f * e; sp[t * H1 + (h)] = __expf(e);
            DOH(a0.x, 0) DOH(a0.y, 1) DOH(a0.z, 2) DOH(a0.w, 3)
            DOH(a1.x, 4) DOH(a1.y, 5) DOH(a1.z, 6) DOH(a1.w, 7)
            DOH(a2.x, 8) DOH(a2.y, 9)
#undef DOH
        }
        __syncthreads();
        if (t < 90) {
            const char* hb = (const char*)g_h1h + 8 * t;  // features 4t..4t+3
            int e = 0;
            for (; e + 4 <= m; e += 4) {
                int s0 = ssrcs[e],     s1 = ssrcs[e + 1];
                int s2 = ssrcs[e + 2], s3 = ssrcs[e + 3];
                u64 w0 = *(const u64*)(hb + (size_t)s0 * (D1 * 2));
                u64 w1 = *(const u64*)(hb + (size_t)s1 * (D1 * 2));
                u64 w2 = *(const u64*)(hb + (size_t)s2 * (D1 * 2));
                u64 w3 = *(const u64*)(hb + (size_t)s3 * (D1 * 2));
                float p0 = sp[(e)     * H1 + head];
                float p1 = sp[(e + 1) * H1 + head];
                float p2 = sp[(e + 2) * H1 + head];
                float p3 = sp[(e + 3) * H1 + head];
                u64 q0 = pack2(p0, p0), q1 = pack2(p1, p1);
                u64 q2 = pack2(p2, p2), q3 = pack2(p3, p3);
                acc01 = ffma2(h2_to_f32x2((unsigned)w0),         q0, acc01);
                acc23 = ffma2(h2_to_f32x2((unsigned)(w0 >> 32)), q0, acc23);
                acc01 = ffma2(h2_to_f32x2((unsigned)w1),         q1, acc01);
                acc23 = ffma2(h2_to_f32x2((unsigned)(w1 >> 32)), q1, acc23);
                acc01 = ffma2(h2_to_f32x2((unsigned)w2),         q2, acc01);
                acc23 = ffma2(h2_to_f32x2((unsigned)(w2 >> 32)), q2, acc23);
                acc01 = ffma2(h2_to_f32x2((unsigned)w3),         q3, acc01);
                acc23 = ffma2(h2_to_f32x2((unsigned)(w3 >> 32)), q3, acc23);
            }
            for (; e < m; e++) {
                int s0 = ssrcs[e];
                float p0 = sp[e * H1 + head];
                u64 w0 = *(const u64*)(hb + (size_t)s0 * (D1 * 2));
                u64 q0 = pack2(p0, p0);
                acc01 = ffma2(h2_to_f32x2((unsigned)w0),         q0, acc01);
                acc23 = ffma2(h2_to_f32x2((unsigned)(w0 >> 32)), q0, acc23);
            }
        } else if (t >= 90 && t < 100) {
            int h = t - 90;
            for (int e = 0; e < m; e++) hsum += sp[e * H1 + h];
        }
    }
    if (t >= 90 && t < 100) ssum[t - 90] = hsum;
    __syncthreads();
    if (t < 90) {
        float rs = 1.0f / (ssum[head] + 1e-16f);
        float2 v01 = unpack2(acc01);
        float2 v23 = unpack2(acc23);
        float4 bv = *(const float4*)(b1 + 4 * t);
        float4 o;
        o.x = v01.x * rs + bv.x;
        o.y = v01.y * rs + bv.y;
        o.z = v23.x * rs + bv.z;
        o.w = v23.y * rs + bv.w;
        o.x = (o.x > 0.f) ? o.x : (__expf(o.x) - 1.f);
        o.y = (o.y > 0.f) ? o.y : (__expf(o.y) - 1.f);
        o.z = (o.z > 0.f) ? o.z : (__expf(o.z) - 1.f);
        o.w = (o.w > 0.f) ? o.w : (__expf(o.w) - 1.f);
        *(float4*)(g_h1act + (size_t)node * D1 + 4 * t) = o;
    }
}

// ---------------- layer 2 GEMM + fused al2 (fp16 h2pre out) ----------------
#define MM2_N 32
#define MM2_STRIDE 36
#define YS_STRIDE 132
__global__ void mm2_kernel(const float* __restrict__ W2,
                           const float* __restrict__ asrc2,
                           const float* __restrict__ adst2) {
    extern __shared__ float smem_[];
    float* xs = smem_;                          // [D1][36]
    float* ys = smem_ + D1 * MM2_STRIDE;        // [32][132]
    int n0 = blockIdx.x * MM2_N;
    int t = threadIdx.x;                        // 128
    for (int i = t; i < MM2_N * D1; i += 128) {
        int n = i / D1, k = i % D1;
        float v = (n0 + n < NN) ? g_h1act[(size_t)(n0 + n) * D1 + k] : 0.f;
        xs[k * MM2_STRIDE + n] = v;
    }
    __syncthreads();
    u64 acc[MM2_N / 2];
#pragma unroll
    for (int p = 0; p < MM2_N / 2; p++) acc[p] = 0;
    for (int k = 0; k < D1; k++) {
        float w = W2[k * D2 + t];
        u64 wf2 = pack2(w, w);
        const ulonglong2* row = (const ulonglong2*)(xs + k * MM2_STRIDE);
#pragma unroll
        for (int q = 0; q < MM2_N / 4; q++) {
            ulonglong2 v = row[q];
            acc[2 * q]     = ffma2(v.x, wf2, acc[2 * q]);
            acc[2 * q + 1] = ffma2(v.y, wf2, acc[2 * q + 1]);
        }
    }
#pragma unroll
    for (int p = 0; p < MM2_N / 2; p++) {
        float2 a = unpack2(acc[p]);
        int n = n0 + 2 * p;
        if (n < NN)     g_h2h[(size_t)n * D2 + t] = __float2half(a.x);
        if (n + 1 < NN) g_h2h[(size_t)(n + 1) * D2 + t] = __float2half(a.y);
        ys[(2 * p) * YS_STRIDE + t]     = a.x;
        ys[(2 * p + 1) * YS_STRIDE + t] = a.y;
    }
    __syncthreads();
    {
        int n = t >> 2, c0 = (t & 3) * 32;
        float ss = 0.f, sd = 0.f;
        const float* yr = ys + n * YS_STRIDE;
        for (int k = c0; k < c0 + 32; k++) {
            float v = yr[k];
            ss = fmaf(v, asrc2[k], ss);
            sd = fmaf(v, adst2[k], sd);
        }
        ss += __shfl_xor_sync(0xffffffffu, ss, 1);
        ss += __shfl_xor_sync(0xffffffffu, ss, 2);
        sd += __shfl_xor_sync(0xffffffffu, sd, 1);
        sd += __shfl_xor_sync(0xffffffffu, sd, 2);
        if ((t & 3) == 0 && n0 + n < NN) {
            g_als2[n0 + n] = ss;
            g_ald2[n0 + n] = sd;
        }
    }
}

// ---------------- layer-2 aggregation: warp per node (fp16 gather, MLP=4) ---------
__global__ void agg2_kernel(const float* __restrict__ b2) {
    int node = blockIdx.x * 4 + (threadIdx.x >> 5);
    int lane = threadIdx.x & 31;
    float aldn = g_ald2[node];
    int deg = g_deg[node];
    int start = g_rowstart[node] - deg;
    u64 acc01 = 0, acc23 = 0;
    float psum = 0.f;
    const char* hb = (const char*)g_h2h + 8 * lane;   // features 4*lane..4*lane+3
    for (int base = 0; base < deg; base += 32) {
        int m = min(32, deg - base);
        int s = 0; float p = 0.f;
        if (lane < m) {
            s = g_ssrc[start + base + lane];
            float e = g_als2[s] + aldn;
            e = (e > 0.f) ? e : 0.2f * e;
            p = __expf(e);
        }
        psum += p;
        int j = 0;
        for (; j + 4 <= m; j += 4) {
            int   s0 = __shfl_sync(0xffffffffu, s, j);
            int   s1 = __shfl_sync(0xffffffffu, s, j + 1);
            int   s2 = __shfl_sync(0xffffffffu, s, j + 2);
            int   s3 = __shfl_sync(0xffffffffu, s, j + 3);
            u64 w0 = *(const u64*)(hb + (size_t)s0 * (D2 * 2));
            u64 w1 = *(const u64*)(hb + (size_t)s1 * (D2 * 2));
            u64 w2 = *(const u64*)(hb + (size_t)s2 * (D2 * 2));
            u64 w3 = *(const u64*)(hb + (size_t)s3 * (D2 * 2));
            float p0 = __shfl_sync(0xffffffffu, p, j);
            float p1 = __shfl_sync(0xffffffffu, p, j + 1);
            float p2 = __shfl_sync(0xffffffffu, p, j + 2);
            float p3 = __shfl_sync(0xffffffffu, p, j + 3);
            u64 q0 = pack2(p0, p0), q1 = pack2(p1, p1);
            u64 q2 = pack2(p2, p2), q3 = pack2(p3, p3);
            acc01 = ffma2(h2_to_f32x2((unsigned)w0),         q0, acc01);
            acc23 = ffma2(h2_to_f32x2((unsigned)(w0 >> 32)), q0, acc23);
            acc01 = ffma2(h2_to_f32x2((unsigned)w1),         q1, acc01);
            acc23 = ffma2(h2_to_f32x2((unsigned)(w1 >> 32)), q1, acc23);
            acc01 = ffma2(h2_to_f32x2((unsigned)w2),         q2, acc01);
            acc23 = ffma2(h2_to_f32x2((unsigned)(w2 >> 32)), q2, acc23);
            acc01 = ffma2(h2_to_f32x2((unsigned)w3),         q3, acc01);
            acc23 = ffma2(h2_to_f32x2((unsigned)(w3 >> 32)), q3, acc23);
        }
        for (; j < m; j++) {
            int   s0 = __shfl_sync(0xffffffffu, s, j);
            float p0 = __shfl_sync(0xffffffffu, p, j);
            u64 w0 = *(const u64*)(hb + (size_t)s0 * (D2 * 2));
            u64 q0 = pack2(p0, p0);
            acc01 = ffma2(h2_to_f32x2((unsigned)w0),         q0, acc01);
            acc23 = ffma2(h2_to_f32x2((unsigned)(w0 >> 32)), q0, acc23);
        }
    }
#pragma unroll
    for (int off = 16; off; off >>= 1)
        psum += __shfl_xor_sync(0xffffffffu, psum, off);
    float rs = 1.0f / (psum + 1e-16f);
    float2 v01 = unpack2(acc01);
    float2 v23 = unpack2(acc23);
    float4 bv = *(const float4*)(b2 + 4 * lane);
    float4 o;
    o.x = fmaxf(v01.x * rs + bv.x, 0.f);
    o.y = fmaxf(v01.y * rs + bv.y, 0.f);
    o.z = fmaxf(v23.x * rs + bv.z, 0.f);
    o.w = fmaxf(v23.y * rs + bv.w, 0.f);
    *(float4*)(g_h2act + (size_t)node * D2 + 4 * lane) = o;
}

// ---------------- pool (sorted batch) + end-of-call cleanup ----------------
__global__ void pool_kernel(const int* __restrict__ batch) {
    int t = threadIdx.x;                   // 128 = feature
    int n0 = blockIdx.x * 128;
    int n1 = min(n0 + 128, NN);
    float cur = 0.f;                       // values >= 0 (post-relu)
    int curb = min(max(batch[n0], 0), NG - 1);
    for (int n = n0; n < n1; n++) {
        int b = min(max(batch[n], 0), NG - 1);
        if (b != curb) {
            atomicMax((int*)&g_pool[curb * D2 + t], __float_as_int(cur));
            cur = 0.f;
            curb = b;
        }
        cur = fmaxf(cur, g_h2act[(size_t)n * D2 + t]);
    }
    atomicMax((int*)&g_pool[curb * D2 + t], __float_as_int(cur));
    // cleanup for next call (deg no longer read this call)
    for (int n = n0 + t; n < n1; n += 128) g_deg[n] = 0;
    if (blockIdx.x == 0 && t < 64) {
        g_flag[t] = 0; g_inc[t] = 0;
    }
}

__global__ void fc_kernel(const float* __restrict__ fcw,
                          const float* __restrict__ fcb,
                          float* __restrict__ out) {
    int gi = blockIdx.x, t = threadIdx.x;
    __shared__ float gs[D2];
    float gv = g_pool[gi * D2 + t];
    if (!(gv >= 0.f)) gv = 0.f;
    gs[t] = gv;
    __syncthreads();
    float s = 0.f;
    for (int k = 0; k < D2; k++)
        s = fmaf(gs[k], fcw[k * D2 + t], s);
    out[gi * D2 + t] = fmaxf(s + fcb[t], 0.f);
}

// ---------------- launcher ----------------
extern "C" void kernel_launch(void* const* d_in, const int* in_sizes, int n_in,
                              void* d_out, int out_size) {
    const float* x     = (const float*)d_in[0];
    const int*   ei    = (const int*)d_in[1];
    const int*   batch = (const int*)d_in[2];
    const float* W1    = (const float*)d_in[3];
    const float* as1   = (const float*)d_in[4];
    const float* ad1   = (const float*)d_in[5];
    const float* b1    = (const float*)d_in[6];
    const float* W2    = (const float*)d_in[7];
    const float* as2   = (const float*)d_in[8];
    const float* ad2   = (const float*)d_in[9];
    const float* b2    = (const float*)d_in[10];
    const float* fcw   = (const float*)d_in[11];
    const float* fcb   = (const float*)d_in[12];
    float* out = (float*)d_out;

    const int mm2_smem = (D1 * MM2_STRIDE + MM2_N * YS_STRIDE) * 4;
    static bool attr_set = false;
    if (!attr_set) {
        cudaFuncSetAttribute(mm2_kernel,
                             cudaFuncAttributeMaxDynamicSharedMemorySize,
                             mm2_smem);
        attr_set = true;
    }

    convert_kernel<<<(ETOT + 255) / 256, 256>>>(ei, W1, as1, ad1);  // idx 0
    scan_kernel<<<49, 1024>>>();                                    // idx 1
    scatter_kernel<<<(ETOT + 255) / 256, 256>>>();                  // idx 2
    mm1_kernel<<<NN / 16, 384>>>(x, W1);                            // idx 3 (profiled)
    agg1_kernel<<<NN, 128>>>(b1);                                   // idx 4

    mm2_kernel<<<(NN + MM2_N - 1) / MM2_N, 128, mm2_smem>>>(W2, as2, ad2);
    agg2_kernel<<<NN / 4, 128>>>(b2);

    pool_kernel<<<(NN + 127) / 128, 128>>>(batch);
    fc_kernel<<<NG, D2>>>(fcw, fcb, out);
}

// round 11
// speedup vs baseline: 1.1731x; 1.1470x over previous
#include <cuda_runtime.h>
#include <cuda_fp16.h>
#include <math.h>

#define NN    50000
#define NE    800000
#define ETOT  850000     // NE + NN self loops
#define H1    10
#define C1    36
#define D1    360        // H1*C1
#define ALP   12         // padded stride for als1/ald1 rows
#define D2    128
#define NG    128

typedef unsigned long long u64;

__device__ __forceinline__ u64 pack2(float a, float b) {
    u64 r; asm("mov.b64 %0, {%1, %2};" : "=l"(r) : "f"(a), "f"(b)); return r;
}
__device__ __forceinline__ u64 ffma2(u64 a, u64 b, u64 c) {
    u64 d; asm("fma.rn.f32x2 %0, %1, %2, %3;" : "=l"(d) : "l"(a), "l"(b), "l"(c)); return d;
}
__device__ __forceinline__ float2 unpack2(u64 v) {
    float2 r; asm("mov.b64 {%0, %1}, %2;" : "=f"(r.x), "=f"(r.y) : "l"(v)); return r;
}
__device__ __forceinline__ u64 h2_to_f32x2(unsigned h2) {
    float2 f = __half22float2(*(__half2*)&h2);
    return pack2(f.x, f.y);
}

// ---------------- device scratch (zero-initialized at module load) ----------------
__device__ int   g_src[ETOT];
__device__ int   g_dst[ETOT];
__device__ int   g_deg[NN];        // zeroed at end of each call (pool_kernel)
__device__ int   g_rowstart[NN];   // becomes row_end after scatter
__device__ int   g_inc[64];
__device__ int   g_flag[64];
__device__ int   g_ssrc[ETOT];     // src ids in CSR-by-dst order
__device__ float g_va[720];        // folded attention projections [sd][k][h]

__device__ __half g_h1h[(size_t)NN * D1];   // 36 MB (fp16 h1pre)
__device__ float g_als1[NN * ALP];
__device__ float g_ald1[NN * ALP];
__device__ __half g_h1ah[(size_t)NN * D1];  // 36 MB (fp16 h1act)
__device__ __half g_h2h[(size_t)NN * D2];   // 12.8 MB (fp16 h2pre)
__device__ float g_als2[NN];
__device__ float g_ald2[NN];
__device__ float g_h2act[(size_t)NN * D2];  // 25.6 MB
__device__ float g_pool[NG * D2];           // 0-init semantics (values >= 0)

// ---------------- va precompute ----------------
__global__ void va_kernel(const float* __restrict__ W1,
                          const float* __restrict__ as1,
                          const float* __restrict__ ad1) {
    int idx = blockIdx.x * blockDim.x + threadIdx.x;
    if (idx >= 720) return;
    int sd = idx / 360, r = idx % 360;
    int k = r / 10, h = r % 10;
    const float* a = sd ? ad1 : as1;
    float s = 0.f;
    for (int c = 0; c < C1; c++)
        s = fmaf(W1[k * D1 + h * C1 + c], a[h * C1 + c], s);
    g_va[sd * 360 + k * 10 + h] = s;
}

// ---------------- convert edges ----------------
__global__ void convert_kernel(const int* __restrict__ ei) {
    int i = blockIdx.x * blockDim.x + threadIdx.x;
    if (i >= ETOT) return;
    int s, d;
    if (i < NE) {
        s = ei[i]; d = ei[NE + i];
        s = min(max(s, 0), NN - 1);
        d = min(max(d, 0), NN - 1);
    } else {
        s = d = i - NE;                      // self loop
    }
    g_src[i] = s; g_dst[i] = d;
    atomicAdd(&g_deg[d], 1);
}

// ---------------- exclusive scan (49 blocks, chained carry) ----------------
__global__ void scan_kernel() {
    __shared__ int tmp[1024];
    __shared__ int carry_s;
    int b = blockIdx.x, t = threadIdx.x;
    int i = b * 1024 + t;
    int v = (i < NN) ? g_deg[i] : 0;
    tmp[t] = v;
    __syncthreads();
    for (int off = 1; off < 1024; off <<= 1) {
        int add = (t >= off) ? tmp[t - off] : 0;
        __syncthreads();
        tmp[t] += add;
        __syncthreads();
    }
    if (t == 0) {
        int total = tmp[1023];
        int carry = 0;
        if (b > 0) {
            while (atomicAdd(&g_flag[b - 1], 0) == 0) { }
            carry = atomicAdd(&g_inc[b - 1], 0);
        }
        g_inc[b] = carry + total;
        __threadfence();
        atomicExch(&g_flag[b], 1);
        carry_s = carry;
    }
    __syncthreads();
    if (i < NN) g_rowstart[i] = carry_s + tmp[t] - v;   // exclusive global
}

// ---------------- scatter (rowstart doubles as cursor -> becomes row_end) ---------
__global__ void scatter_kernel() {
    int i = blockIdx.x * blockDim.x + threadIdx.x;
    if (i >= ETOT) return;
    int d = g_dst[i];
    int pos = atomicAdd(&g_rowstart[d], 1);
    g_ssrc[pos] = g_src[i];
}

// ---------------- layer 1 GEMM: [h1h | als | ald] = x @ [W1 | va] ----------------
__global__ void mm1_kernel(const float* __restrict__ x,
                           const float* __restrict__ W1) {
    // 16 nodes per block, 384 threads (one output column each; 360 feat + 20 attn)
    int n0 = blockIdx.x * 16;
    int t = threadIdx.x;
    __shared__ u64 xsp[C1 * 8];   // [k][pair m]
    if (t < 288) {
        int k = t >> 3, m = t & 7;
        float a = x[(size_t)(n0 + 2 * m) * C1 + k];
        float b = x[(size_t)(n0 + 2 * m + 1) * C1 + k];
        xsp[k * 8 + m] = pack2(a, b);
    }
    __syncthreads();
    const float* wptr; int wstride;
    if (t < D1)            { wptr = W1 + t; wstride = D1; }
    else if (t < D1 + 20)  { int j = t - D1; wptr = g_va + (j & 1) * 360 + (j >> 1); wstride = 10; }
    else                   { wptr = W1 + t - 24; wstride = D1; }   // idle lanes, harmless
    u64 acc[8] = {0, 0, 0, 0, 0, 0, 0, 0};
    for (int k = 0; k < C1; k++) {
        float w = wptr[k * wstride];
        u64 ww = pack2(w, w);
        const ulonglong2* row = (const ulonglong2*)(xsp + k * 8);
#pragma unroll
        for (int q = 0; q < 4; q++) {
            ulonglong2 v = row[q];
            acc[2 * q]     = ffma2(v.x, ww, acc[2 * q]);
            acc[2 * q + 1] = ffma2(v.y, ww, acc[2 * q + 1]);
        }
    }
    if (t < D1) {
#pragma unroll
        for (int m = 0; m < 8; m++) {
            float2 v = unpack2(acc[m]);
            g_h1h[(size_t)(n0 + 2 * m) * D1 + t]     = __float2half(v.x);
            g_h1h[(size_t)(n0 + 2 * m + 1) * D1 + t] = __float2half(v.y);
        }
    } else if (t < D1 + 20) {
        int j = t - D1, h = j >> 1;
        float* dst = (j & 1) ? g_ald1 : g_als1;
#pragma unroll
        for (int m = 0; m < 8; m++) {
            float2 v = unpack2(acc[m]);
            dst[(n0 + 2 * m) * ALP + h]     = v.x;
            dst[(n0 + 2 * m + 1) * ALP + h] = v.y;
        }
    }
}

// ---------------- layer-1 aggregation, 4 nodes per block (fp16 in/out) ------------
__global__ void agg1_kernel(const float* __restrict__ b1) {
    int t = threadIdx.x;            // 128
    __shared__ int   ssrcs[128];
    __shared__ float sp[128 * H1];  // 5 KB
    __shared__ float aldn[H1];
    __shared__ float ssum[H1];
    const int head = (t < 90) ? (t / 9) : 0;

    for (int nd = 0; nd < 4; nd++) {
        int node = blockIdx.x * 4 + nd;
        __syncthreads();
        if (t < H1) aldn[t] = g_ald1[node * ALP + t];

        int deg = g_deg[node];
        int start = g_rowstart[node] - deg;   // rowstart holds row_end post-scatter
        u64 acc01 = 0, acc23 = 0;
        float hsum = 0.f;

        for (int base = 0; base < deg; base += 128) {
            int m = min(128, deg - base);
            __syncthreads();
            if (t < m) {
                int s = g_ssrc[start + base + t];
                ssrcs[t] = s;
                const float* ar = &g_als1[(size_t)s * ALP];
                float4 a0 = *(const float4*)ar;
                float4 a1 = *(const float4*)(ar + 4);
                float2 a2 = *(const float2*)(ar + 8);
                float e;
#define DOH(val, h) e = (val) + aldn[h]; e = (e > 0.f) ? e : 0.2f * e; sp[t * H1 + (h)] = __expf(e);
                DOH(a0.x, 0) DOH(a0.y, 1) DOH(a0.z, 2) DOH(a0.w, 3)
                DOH(a1.x, 4) DOH(a1.y, 5) DOH(a1.z, 6) DOH(a1.w, 7)
                DOH(a2.x, 8) DOH(a2.y, 9)
#undef DOH
            }
            __syncthreads();
            if (t < 90) {
                const char* hb = (const char*)g_h1h + 8 * t;  // features 4t..4t+3
                int e = 0;
                for (; e + 2 <= m; e += 2) {
                    int s0 = ssrcs[e], s1 = ssrcs[e + 1];
                    float p0 = sp[e * H1 + head];
                    float p1 = sp[(e + 1) * H1 + head];
                    u64 w0 = *(const u64*)(hb + (size_t)s0 * (D1 * 2));
                    u64 w1 = *(const u64*)(hb + (size_t)s1 * (D1 * 2));
                    u64 q0 = pack2(p0, p0), q1 = pack2(p1, p1);
                    acc01 = ffma2(h2_to_f32x2((unsigned)w0),         q0, acc01);
                    acc23 = ffma2(h2_to_f32x2((unsigned)(w0 >> 32)), q0, acc23);
                    acc01 = ffma2(h2_to_f32x2((unsigned)w1),         q1, acc01);
                    acc23 = ffma2(h2_to_f32x2((unsigned)(w1 >> 32)), q1, acc23);
                }
                if (e < m) {
                    int s0 = ssrcs[e];
                    float p0 = sp[e * H1 + head];
                    u64 w0 = *(const u64*)(hb + (size_t)s0 * (D1 * 2));
                    u64 q0 = pack2(p0, p0);
                    acc01 = ffma2(h2_to_f32x2((unsigned)w0),         q0, acc01);
                    acc23 = ffma2(h2_to_f32x2((unsigned)(w0 >> 32)), q0, acc23);
                }
            } else if (t >= 90 && t < 100) {
                int h = t - 90;
                for (int e = 0; e < m; e++) hsum += sp[e * H1 + h];
            }
        }
        if (t >= 90 && t < 100) ssum[t - 90] = hsum;
        __syncthreads();
        if (t < 90) {
            float rs = 1.0f / (ssum[head] + 1e-16f);
            float2 v01 = unpack2(acc01);
            float2 v23 = unpack2(acc23);
            float4 bv = *(const float4*)(b1 + 4 * t);
            float4 o;
            o.x = v01.x * rs + bv.x;
            o.y = v01.y * rs + bv.y;
            o.z = v23.x * rs + bv.z;
            o.w = v23.y * rs + bv.w;
            o.x = (o.x > 0.f) ? o.x : (__expf(o.x) - 1.f);
            o.y = (o.y > 0.f) ? o.y : (__expf(o.y) - 1.f);
            o.z = (o.z > 0.f) ? o.z : (__expf(o.z) - 1.f);
            o.w = (o.w > 0.f) ? o.w : (__expf(o.w) - 1.f);
            __half2 ha = __floats2half2_rn(o.x, o.y);
            __half2 hbp = __floats2half2_rn(o.z, o.w);
            unsigned ua = *(unsigned*)&ha, ub = *(unsigned*)&hbp;
            *(uint2*)(g_h1ah + (size_t)node * D1 + 4 * t) = make_uint2(ua, ub);
        }
    }
}

// ---------------- layer 2 GEMM + fused al2 (fp16 in/out, smem reuse) --------------
#define MM2_N 32
#define MM2_STRIDE 36
#define YS_STRIDE 132
__global__ void mm2_kernel(const float* __restrict__ W2,
                           const float* __restrict__ asrc2,
                           const float* __restrict__ adst2) {
    extern __shared__ float smem_[];
    float* xs = smem_;                          // [D1][36] = 51.8 KB
    int n0 = blockIdx.x * MM2_N;
    int t = threadIdx.x;                        // 128
    for (int i = t; i < MM2_N * (D1 / 2); i += 128) {   // 5760 half2 loads
        int n = i / (D1 / 2), kp = i % (D1 / 2), k = 2 * kp;
        float2 f = make_float2(0.f, 0.f);
        if (n0 + n < NN)
            f = __half22float2(*(const __half2*)(g_h1ah + (size_t)(n0 + n) * D1 + k));
        xs[k * MM2_STRIDE + n] = f.x;
        xs[(k + 1) * MM2_STRIDE + n] = f.y;
    }
    __syncthreads();
    u64 acc[MM2_N / 2];
#pragma unroll
    for (int p = 0; p < MM2_N / 2; p++) acc[p] = 0;
    for (int k = 0; k < D1; k++) {
        float w = W2[k * D2 + t];
        u64 wf2 = pack2(w, w);
        const ulonglong2* row = (const ulonglong2*)(xs + k * MM2_STRIDE);
#pragma unroll
        for (int q = 0; q < MM2_N / 4; q++) {
            ulonglong2 v = row[q];
            acc[2 * q]     = ffma2(v.x, wf2, acc[2 * q]);
            acc[2 * q + 1] = ffma2(v.y, wf2, acc[2 * q + 1]);
        }
    }
    __syncthreads();                 // xs no longer needed; reuse as ys
    float* ys = smem_;               // [32][132] = 16.9 KB (fits in xs space)
#pragma unroll
    for (int p = 0; p < MM2_N / 2; p++) {
        float2 a = unpack2(acc[p]);
        int n = n0 + 2 * p;
        if (n < NN)     g_h2h[(size_t)n * D2 + t] = __float2half(a.x);
        if (n + 1 < NN) g_h2h[(size_t)(n + 1) * D2 + t] = __float2half(a.y);
        ys[(2 * p) * YS_STRIDE + t]     = a.x;
        ys[(2 * p + 1) * YS_STRIDE + t] = a.y;
    }
    __syncthreads();
    {
        int n = t >> 2, c0 = (t & 3) * 32;
        float ss = 0.f, sd = 0.f;
        const float* yr = ys + n * YS_STRIDE;
        for (int k = c0; k < c0 + 32; k++) {
            float v = yr[k];
            ss = fmaf(v, asrc2[k], ss);
            sd = fmaf(v, adst2[k], sd);
        }
        ss += __shfl_xor_sync(0xffffffffu, ss, 1);
        ss += __shfl_xor_sync(0xffffffffu, ss, 2);
        sd += __shfl_xor_sync(0xffffffffu, sd, 1);
        sd += __shfl_xor_sync(0xffffffffu, sd, 2);
        if ((t & 3) == 0 && n0 + n < NN) {
            g_als2[n0 + n] = ss;
            g_ald2[n0 + n] = sd;
        }
    }
}

// ---------------- layer-2 aggregation: warp per node (fp16 gather) ----------------
__global__ void agg2_kernel(const float* __restrict__ b2) {
    int node = blockIdx.x * 4 + (threadIdx.x >> 5);
    int lane = threadIdx.x & 31;
    float aldn = g_ald2[node];
    int deg = g_deg[node];
    int start = g_rowstart[node] - deg;
    u64 acc01 = 0, acc23 = 0;
    float psum = 0.f;
    const char* hb = (const char*)g_h2h + 8 * lane;   // features 4*lane..4*lane+3
    for (int base = 0; base < deg; base += 32) {
        int m = min(32, deg - base);
        int s = 0; float p = 0.f;
        if (lane < m) {
            s = g_ssrc[start + base + lane];
            float e = g_als2[s] + aldn;
            e = (e > 0.f) ? e : 0.2f * e;
            p = __expf(e);
        }
        psum += p;
        int j = 0;
        for (; j + 4 <= m; j += 4) {
            int   s0 = __shfl_sync(0xffffffffu, s, j);
            int   s1 = __shfl_sync(0xffffffffu, s, j + 1);
            int   s2 = __shfl_sync(0xffffffffu, s, j + 2);
            int   s3 = __shfl_sync(0xffffffffu, s, j + 3);
            u64 w0 = *(const u64*)(hb + (size_t)s0 * (D2 * 2));
            u64 w1 = *(const u64*)(hb + (size_t)s1 * (D2 * 2));
            u64 w2 = *(const u64*)(hb + (size_t)s2 * (D2 * 2));
            u64 w3 = *(const u64*)(hb + (size_t)s3 * (D2 * 2));
            float p0 = __shfl_sync(0xffffffffu, p, j);
            float p1 = __shfl_sync(0xffffffffu, p, j + 1);
            float p2 = __shfl_sync(0xffffffffu, p, j + 2);
            float p3 = __shfl_sync(0xffffffffu, p, j + 3);
            u64 q0 = pack2(p0, p0), q1 = pack2(p1, p1);
            u64 q2 = pack2(p2, p2), q3 = pack2(p3, p3);
            acc01 = ffma2(h2_to_f32x2((unsigned)w0),         q0, acc01);
            acc23 = ffma2(h2_to_f32x2((unsigned)(w0 >> 32)), q0, acc23);
            acc01 = ffma2(h2_to_f32x2((unsigned)w1),         q1, acc01);
            acc23 = ffma2(h2_to_f32x2((unsigned)(w1 >> 32)), q1, acc23);
            acc01 = ffma2(h2_to_f32x2((unsigned)w2),         q2, acc01);
            acc23 = ffma2(h2_to_f32x2((unsigned)(w2 >> 32)), q2, acc23);
            acc01 = ffma2(h2_to_f32x2((unsigned)w3),         q3, acc01);
            acc23 = ffma2(h2_to_f32x2((unsigned)(w3 >> 32)), q3, acc23);
        }
        for (; j < m; j++) {
            int   s0 = __shfl_sync(0xffffffffu, s, j);
            float p0 = __shfl_sync(0xffffffffu, p, j);
            u64 w0 = *(const u64*)(hb + (size_t)s0 * (D2 * 2));
            u64 q0 = pack2(p0, p0);
            acc01 = ffma2(h2_to_f32x2((unsigned)w0),         q0, acc01);
            acc23 = ffma2(h2_to_f32x2((unsigned)(w0 >> 32)), q0, acc23);
        }
    }
#pragma unroll
    for (int off = 16; off; off >>= 1)
        psum += __shfl_xor_sync(0xffffffffu, psum, off);
    float rs = 1.0f / (psum + 1e-16f);
    float2 v01 = unpack2(acc01);
    float2 v23 = unpack2(acc23);
    float4 bv = *(const float4*)(b2 + 4 * lane);
    float4 o;
    o.x = fmaxf(v01.x * rs + bv.x, 0.f);
    o.y = fmaxf(v01.y * rs + bv.y, 0.f);
    o.z = fmaxf(v23.x * rs + bv.z, 0.f);
    o.w = fmaxf(v23.y * rs + bv.w, 0.f);
    *(float4*)(g_h2act + (size_t)node * D2 + 4 * lane) = o;
}

// ---------------- pool (sorted batch) + end-of-call cleanup ----------------
__global__ void pool_kernel(const int* __restrict__ batch) {
    int t = threadIdx.x;                   // 128 = feature
    int n0 = blockIdx.x * 128;
    int n1 = min(n0 + 128, NN);
    float cur = 0.f;                       // values >= 0 (post-relu)
    int curb = min(max(batch[n0], 0), NG - 1);
    for (int n = n0; n < n1; n++) {
        int b = min(max(batch[n], 0), NG - 1);
        if (b != curb) {
            atomicMax((int*)&g_pool[curb * D2 + t], __float_as_int(cur));
            cur = 0.f;
            curb = b;
        }
        cur = fmaxf(cur, g_h2act[(size_t)n * D2 + t]);
    }
    atomicMax((int*)&g_pool[curb * D2 + t], __float_as_int(cur));
    // cleanup for next call (deg no longer read this call)
    for (int n = n0 + t; n < n1; n += 128) g_deg[n] = 0;
    if (blockIdx.x == 0 && t < 64) {
        g_flag[t] = 0; g_inc[t] = 0;
    }
}

__global__ void fc_kernel(const float* __restrict__ fcw,
                          const float* __restrict__ fcb,
                          float* __restrict__ out) {
    int gi = blockIdx.x, t = threadIdx.x;
    __shared__ float gs[D2];
    float gv = g_pool[gi * D2 + t];
    if (!(gv >= 0.f)) gv = 0.f;
    gs[t] = gv;
    __syncthreads();
    float s = 0.f;
    for (int k = 0; k < D2; k++)
        s = fmaf(gs[k], fcw[k * D2 + t], s);
    out[gi * D2 + t] = fmaxf(s + fcb[t], 0.f);
}

// ---------------- launcher ----------------
extern "C" void kernel_launch(void* const* d_in, const int* in_sizes, int n_in,
                              void* d_out, int out_size) {
    const float* x     = (const float*)d_in[0];
    const int*   ei    = (const int*)d_in[1];
    const int*   batch = (const int*)d_in[2];
    const float* W1    = (const float*)d_in[3];
    const float* as1   = (const float*)d_in[4];
    const float* ad1   = (const float*)d_in[5];
    const float* b1    = (const float*)d_in[6];
    const float* W2    = (const float*)d_in[7];
    const float* as2   = (const float*)d_in[8];
    const float* ad2   = (const float*)d_in[9];
    const float* b2    = (const float*)d_in[10];
    const float* fcw   = (const float*)d_in[11];
    const float* fcb   = (const float*)d_in[12];
    float* out = (float*)d_out;

    const int mm2_smem = D1 * MM2_STRIDE * 4;   // ys reuses xs
    static bool attr_set = false;
    if (!attr_set) {
        cudaFuncSetAttribute(mm2_kernel,
                             cudaFuncAttributeMaxDynamicSharedMemorySize,
                             mm2_smem);
        attr_set = true;
    }

    va_kernel<<<3, 256>>>(W1, as1, ad1);                            // idx 0
    mm1_kernel<<<NN / 16, 384>>>(x, W1);                            // idx 1 (indep of CSR)
    convert_kernel<<<(ETOT + 255) / 256, 256>>>(ei);                // idx 2
    scan_kernel<<<49, 1024>>>();                                    // idx 3 (profiled)
    scatter_kernel<<<(ETOT + 255) / 256, 256>>>();                  // idx 4
    agg1_kernel<<<NN / 4, 128>>>(b1);                               // idx 5

    mm2_kernel<<<(NN + MM2_N - 1) / MM2_N, 128, mm2_smem>>>(W2, as2, ad2);
    agg2_kernel<<<NN / 4, 128>>>(b2);

    pool_kernel<<<(NN + 127) / 128, 128>>>(batch);
    fc_kernel<<<NG, D2>>>(fcw, fcb, out);
}

// round 12
// speedup vs baseline: 1.2202x; 1.0401x over previous
#include <cuda_runtime.h>
#include <cuda_fp16.h>
#include <math.h>

#define NN    50000
#define NE    800000
#define ETOT  850000     // NE + NN self loops
#define H1    10
#define C1    36
#define D1    360        // H1*C1
#define ALP   12         // padded stride for als1/ald1 rows
#define D2    128
#define NG    128

typedef unsigned long long u64;

__device__ __forceinline__ u64 pack2(float a, float b) {
    u64 r; asm("mov.b64 %0, {%1, %2};" : "=l"(r) : "f"(a), "f"(b)); return r;
}
__device__ __forceinline__ u64 ffma2(u64 a, u64 b, u64 c) {
    u64 d; asm("fma.rn.f32x2 %0, %1, %2, %3;" : "=l"(d) : "l"(a), "l"(b), "l"(c)); return d;
}
__device__ __forceinline__ float2 unpack2(u64 v) {
    float2 r; asm("mov.b64 {%0, %1}, %2;" : "=f"(r.x), "=f"(r.y) : "l"(v)); return r;
}
__device__ __forceinline__ u64 h2_to_f32x2(unsigned h2) {
    float2 f = __half22float2(*(__half2*)&h2);
    return pack2(f.x, f.y);
}

// ---------------- device scratch (zero-initialized at module load) ----------------
__device__ int   g_src[ETOT];
__device__ int   g_dst[ETOT];
__device__ int   g_deg[NN];        // zeroed at end of each call (pool_kernel)
__device__ int   g_rowstart[NN];   // becomes row_end after scatter
__device__ int   g_inc[64];        // per-block sums (overwritten each call)
__device__ int   g_ssrc[ETOT];     // src ids in CSR-by-dst order
__device__ float g_va[720];        // folded attention projections [sd][k][h]

__device__ __half g_h1h[(size_t)NN * D1];   // 36 MB (fp16 h1pre)
__device__ float g_als1[NN * ALP];
__device__ float g_ald1[NN * ALP];
__device__ __half g_h1ah[(size_t)NN * D1];  // 36 MB (fp16 h1act)
__device__ __half g_h2h[(size_t)NN * D2];   // 12.8 MB (fp16 h2pre)
__device__ float g_als2[NN];
__device__ float g_ald2[NN];
__device__ float g_h2act[(size_t)NN * D2];  // 25.6 MB
__device__ float g_pool[NG * D2];           // 0-init semantics (values >= 0)

// ---------------- va precompute ----------------
__global__ void va_kernel(const float* __restrict__ W1,
                          const float* __restrict__ as1,
                          const float* __restrict__ ad1) {
    int idx = blockIdx.x * blockDim.x + threadIdx.x;
    if (idx >= 720) return;
    int sd = idx / 360, r = idx % 360;
    int k = r / 10, h = r % 10;
    const float* a = sd ? ad1 : as1;
    float s = 0.f;
    for (int c = 0; c < C1; c++)
        s = fmaf(W1[k * D1 + h * C1 + c], a[h * C1 + c], s);
    g_va[sd * 360 + k * 10 + h] = s;
}

// ---------------- convert edges ----------------
__global__ void convert_kernel(const int* __restrict__ ei) {
    int i = blockIdx.x * blockDim.x + threadIdx.x;
    if (i >= ETOT) return;
    int s, d;
    if (i < NE) {
        s = ei[i]; d = ei[NE + i];
        s = min(max(s, 0), NN - 1);
        d = min(max(d, 0), NN - 1);
    } else {
        s = d = i - NE;                      // self loop
    }
    g_src[i] = s; g_dst[i] = d;
    atomicAdd(&g_deg[d], 1);
}

// ---------------- 3-phase exclusive scan (shuffle-based, no carry chain) ----------
__global__ void scanA_kernel() {
    __shared__ int wsum[32];
    int b = blockIdx.x, t = threadIdx.x;
    int lane = t & 31, wid = t >> 5;
    int i = b * 1024 + t;
    int v = (i < NN) ? g_deg[i] : 0;
    // warp inclusive scan
    int x = v;
#pragma unroll
    for (int off = 1; off < 32; off <<= 1) {
        int y = __shfl_up_sync(0xffffffffu, x, off);
        if (lane >= off) x += y;
    }
    if (lane == 31) wsum[wid] = x;
    __syncthreads();
    if (wid == 0) {
        int w = wsum[lane];
#pragma unroll
        for (int off = 1; off < 32; off <<= 1) {
            int y = __shfl_up_sync(0xffffffffu, w, off);
            if (lane >= off) w += y;
        }
        wsum[lane] = w;
    }
    __syncthreads();
    int incl = x + (wid ? wsum[wid - 1] : 0);
    if (i < NN) g_rowstart[i] = incl - v;       // exclusive (local)
    if (t == 1023) g_inc[b] = incl;             // block total
}

__global__ void scanB_kernel() {                // 1 block, 64 threads
    int t = threadIdx.x;
    int lane = t & 31, wid = t >> 5;
    __shared__ int w0sum;
    int v = (t < 49) ? g_inc[t] : 0;
    int x = v;
#pragma unroll
    for (int off = 1; off < 32; off <<= 1) {
        int y = __shfl_up_sync(0xffffffffu, x, off);
        if (lane >= off) x += y;
    }
    if (wid == 0 && lane == 31) w0sum = x;
    __syncthreads();
    int incl = x + (wid ? w0sum : 0);
    if (t < 49) g_inc[t] = incl - v;            // exclusive block offsets
}

__global__ void scanC_kernel() {
    int i = blockIdx.x * blockDim.x + threadIdx.x;
    if (i < NN) g_rowstart[i] += g_inc[i >> 10];
}

// ---------------- scatter (rowstart doubles as cursor -> becomes row_end) ---------
__global__ void scatter_kernel() {
    int i = blockIdx.x * blockDim.x + threadIdx.x;
    if (i >= ETOT) return;
    int d = g_dst[i];
    int pos = atomicAdd(&g_rowstart[d], 1);
    g_ssrc[pos] = g_src[i];
}

// ---------------- layer 1 GEMM: [h1h | als | ald] = x @ [W1 | va] ----------------
__global__ void mm1_kernel(const float* __restrict__ x,
                           const float* __restrict__ W1) {
    // 16 nodes per block, 384 threads (one output column each; 360 feat + 20 attn)
    int n0 = blockIdx.x * 16;
    int t = threadIdx.x;
    __shared__ u64 xsp[C1 * 8];   // [k][pair m]
    if (t < 288) {
        int k = t >> 3, m = t & 7;
        float a = x[(size_t)(n0 + 2 * m) * C1 + k];
        float b = x[(size_t)(n0 + 2 * m + 1) * C1 + k];
        xsp[k * 8 + m] = pack2(a, b);
    }
    __syncthreads();
    const float* wptr; int wstride;
    if (t < D1)            { wptr = W1 + t; wstride = D1; }
    else if (t < D1 + 20)  { int j = t - D1; wptr = g_va + (j & 1) * 360 + (j >> 1); wstride = 10; }
    else                   { wptr = W1 + t - 24; wstride = D1; }   // idle lanes, harmless
    u64 acc[8] = {0, 0, 0, 0, 0, 0, 0, 0};
    for (int k = 0; k < C1; k++) {
        float w = wptr[k * wstride];
        u64 ww = pack2(w, w);
        const ulonglong2* row = (const ulonglong2*)(xsp + k * 8);
#pragma unroll
        for (int q = 0; q < 4; q++) {
            ulonglong2 v = row[q];
            acc[2 * q]     = ffma2(v.x, ww, acc[2 * q]);
            acc[2 * q + 1] = ffma2(v.y, ww, acc[2 * q + 1]);
        }
    }
    if (t < D1) {
#pragma unroll
        for (int m = 0; m < 8; m++) {
            float2 v = unpack2(acc[m]);
            g_h1h[(size_t)(n0 + 2 * m) * D1 + t]     = __float2half(v.x);
            g_h1h[(size_t)(n0 + 2 * m + 1) * D1 + t] = __float2half(v.y);
        }
    } else if (t < D1 + 20) {
        int j = t - D1, h = j >> 1;
        float* dst = (j & 1) ? g_ald1 : g_als1;
#pragma unroll
        for (int m = 0; m < 8; m++) {
            float2 v = unpack2(acc[m]);
            dst[(n0 + 2 * m) * ALP + h]     = v.x;
            dst[(n0 + 2 * m + 1) * ALP + h] = v.y;
        }
    }
}

// ---------------- layer-1 aggregation, 4 nodes per block (fp16 in/out) ------------
__global__ void agg1_kernel(const float* __restrict__ b1) {
    int t = threadIdx.x;            // 128
    __shared__ int   ssrcs[128];
    __shared__ float sp[128 * H1];  // 5 KB
    __shared__ float aldn[H1];
    __shared__ float ssum[H1];
    const int head = (t < 90) ? (t / 9) : 0;

    for (int nd = 0; nd < 4; nd++) {
        int node = blockIdx.x * 4 + nd;
        __syncthreads();
        if (t < H1) aldn[t] = g_ald1[node * ALP + t];

        int deg = g_deg[node];
        int start = g_rowstart[node] - deg;   // rowstart holds row_end post-scatter
        u64 acc01 = 0, acc23 = 0;
        float hsum = 0.f;

        for (int base = 0; base < deg; base += 128) {
            int m = min(128, deg - base);
            __syncthreads();
            if (t < m) {
                int s = g_ssrc[start + base + t];
                ssrcs[t] = s;
                const float* ar = &g_als1[(size_t)s * ALP];
                float4 a0 = *(const float4*)ar;
                float4 a1 = *(const float4*)(ar + 4);
                float2 a2 = *(const float2*)(ar + 8);
                float e;
#define DOH(val, h) e = (val) + aldn[h]; e = (e > 0.f) ? e : 0.2f * e; sp[t * H1 + (h)] = __expf(e);
                DOH(a0.x, 0) DOH(a0.y, 1) DOH(a0.z, 2) DOH(a0.w, 3)
                DOH(a1.x, 4) DOH(a1.y, 5) DOH(a1.z, 6) DOH(a1.w, 7)
                DOH(a2.x, 8) DOH(a2.y, 9)
#undef DOH
            }
            __syncthreads();
            if (t < 90) {
                const char* hb = (const char*)g_h1h + 8 * t;  // features 4t..4t+3
                int e = 0;
                for (; e + 2 <= m; e += 2) {
                    int s0 = ssrcs[e], s1 = ssrcs[e + 1];
                    float p0 = sp[e * H1 + head];
                    float p1 = sp[(e + 1) * H1 + head];
                    u64 w0 = *(const u64*)(hb + (size_t)s0 * (D1 * 2));
                    u64 w1 = *(const u64*)(hb + (size_t)s1 * (D1 * 2));
                    u64 q0 = pack2(p0, p0), q1 = pack2(p1, p1);
                    acc01 = ffma2(h2_to_f32x2((unsigned)w0),         q0, acc01);
                    acc23 = ffma2(h2_to_f32x2((unsigned)(w0 >> 32)), q0, acc23);
                    acc01 = ffma2(h2_to_f32x2((unsigned)w1),         q1, acc01);
                    acc23 = ffma2(h2_to_f32x2((unsigned)(w1 >> 32)), q1, acc23);
                }
                if (e < m) {
                    int s0 = ssrcs[e];
                    float p0 = sp[e * H1 + head];
                    u64 w0 = *(const u64*)(hb + (size_t)s0 * (D1 * 2));
                    u64 q0 = pack2(p0, p0);
                    acc01 = ffma2(h2_to_f32x2((unsigned)w0),         q0, acc01);
                    acc23 = ffma2(h2_to_f32x2((unsigned)(w0 >> 32)), q0, acc23);
                }
            } else if (t >= 90 && t < 100) {
                int h = t - 90;
                for (int e = 0; e < m; e++) hsum += sp[e * H1 + h];
            }
        }
        if (t >= 90 && t < 100) ssum[t - 90] = hsum;
        __syncthreads();
        if (t < 90) {
            float rs = 1.0f / (ssum[head] + 1e-16f);
            float2 v01 = unpack2(acc01);
            float2 v23 = unpack2(acc23);
            float4 bv = *(const float4*)(b1 + 4 * t);
            float4 o;
            o.x = v01.x * rs + bv.x;
            o.y = v01.y * rs + bv.y;
            o.z = v23.x * rs + bv.z;
            o.w = v23.y * rs + bv.w;
            o.x = (o.x > 0.f) ? o.x : (__expf(o.x) - 1.f);
            o.y = (o.y > 0.f) ? o.y : (__expf(o.y) - 1.f);
            o.z = (o.z > 0.f) ? o.z : (__expf(o.z) - 1.f);
            o.w = (o.w > 0.f) ? o.w : (__expf(o.w) - 1.f);
            __half2 ha = __floats2half2_rn(o.x, o.y);
            __half2 hbp = __floats2half2_rn(o.z, o.w);
            unsigned ua = *(unsigned*)&ha, ub = *(unsigned*)&hbp;
            *(uint2*)(g_h1ah + (size_t)node * D1 + 4 * t) = make_uint2(ua, ub);
        }
    }
}

// ---------------- layer 2 GEMM + fused al2 (fp16 in/out, smem reuse) --------------
#define MM2_N 32
#define MM2_STRIDE 36
#define YS_STRIDE 132
__global__ void mm2_kernel(const float* __restrict__ W2,
                           const float* __restrict__ asrc2,
                           const float* __restrict__ adst2) {
    extern __shared__ float smem_[];
    float* xs = smem_;                          // [D1][36] = 51.8 KB
    int n0 = blockIdx.x * MM2_N;
    int t = threadIdx.x;                        // 128
    for (int i = t; i < MM2_N * (D1 / 2); i += 128) {   // half2 loads
        int n = i / (D1 / 2), kp = i % (D1 / 2), k = 2 * kp;
        float2 f = make_float2(0.f, 0.f);
        if (n0 + n < NN)
            f = __half22float2(*(const __half2*)(g_h1ah + (size_t)(n0 + n) * D1 + k));
        xs[k * MM2_STRIDE + n] = f.x;
        xs[(k + 1) * MM2_STRIDE + n] = f.y;
    }
    __syncthreads();
    u64 acc[MM2_N / 2];
#pragma unroll
    for (int p = 0; p < MM2_N / 2; p++) acc[p] = 0;
    for (int k = 0; k < D1; k++) {
        float w = W2[k * D2 + t];
        u64 wf2 = pack2(w, w);
        const ulonglong2* row = (const ulonglong2*)(xs + k * MM2_STRIDE);
#pragma unroll
        for (int q = 0; q < MM2_N / 4; q++) {
            ulonglong2 v = row[q];
            acc[2 * q]     = ffma2(v.x, wf2, acc[2 * q]);
            acc[2 * q + 1] = ffma2(v.y, wf2, acc[2 * q + 1]);
        }
    }
    __syncthreads();                 // xs no longer needed; reuse as ys
    float* ys = smem_;               // [32][132] = 16.9 KB
#pragma unroll
    for (int p = 0; p < MM2_N / 2; p++) {
        float2 a = unpack2(acc[p]);
        int n = n0 + 2 * p;
        if (n < NN)     g_h2h[(size_t)n * D2 + t] = __float2half(a.x);
        if (n + 1 < NN) g_h2h[(size_t)(n + 1) * D2 + t] = __float2half(a.y);
        ys[(2 * p) * YS_STRIDE + t]     = a.x;
        ys[(2 * p + 1) * YS_STRIDE + t] = a.y;
    }
    __syncthreads();
    {
        int n = t >> 2, c0 = (t & 3) * 32;
        float ss = 0.f, sd = 0.f;
        const float* yr = ys + n * YS_STRIDE;
        for (int k = c0; k < c0 + 32; k++) {
            float v = yr[k];
            ss = fmaf(v, asrc2[k], ss);
            sd = fmaf(v, adst2[k], sd);
        }
        ss += __shfl_xor_sync(0xffffffffu, ss, 1);
        ss += __shfl_xor_sync(0xffffffffu, ss, 2);
        sd += __shfl_xor_sync(0xffffffffu, sd, 1);
        sd += __shfl_xor_sync(0xffffffffu, sd, 2);
        if ((t & 3) == 0 && n0 + n < NN) {
            g_als2[n0 + n] = ss;
            g_ald2[n0 + n] = sd;
        }
    }
}

// ---------------- layer-2 aggregation: warp per node (fp16 gather) ----------------
__global__ void agg2_kernel(const float* __restrict__ b2) {
    int node = blockIdx.x * 4 + (threadIdx.x >> 5);
    int lane = threadIdx.x & 31;
    float aldn = g_ald2[node];
    int deg = g_deg[node];
    int start = g_rowstart[node] - deg;
    u64 acc01 = 0, acc23 = 0;
    float psum = 0.f;
    const char* hb = (const char*)g_h2h + 8 * lane;   // features 4*lane..4*lane+3
    for (int base = 0; base < deg; base += 32) {
        int m = min(32, deg - base);
        int s = 0; float p = 0.f;
        if (lane < m) {
            s = g_ssrc[start + base + lane];
            float e = g_als2[s] + aldn;
            e = (e > 0.f) ? e : 0.2f * e;
            p = __expf(e);
        }
        psum += p;
        int j = 0;
        for (; j + 4 <= m; j += 4) {
            int   s0 = __shfl_sync(0xffffffffu, s, j);
            int   s1 = __shfl_sync(0xffffffffu, s, j + 1);
            int   s2 = __shfl_sync(0xffffffffu, s, j + 2);
            int   s3 = __shfl_sync(0xffffffffu, s, j + 3);
            u64 w0 = *(const u64*)(hb + (size_t)s0 * (D2 * 2));
            u64 w1 = *(const u64*)(hb + (size_t)s1 * (D2 * 2));
            u64 w2 = *(const u64*)(hb + (size_t)s2 * (D2 * 2));
            u64 w3 = *(const u64*)(hb + (size_t)s3 * (D2 * 2));
            float p0 = __shfl_sync(0xffffffffu, p, j);
            float p1 = __shfl_sync(0xffffffffu, p, j + 1);
            float p2 = __shfl_sync(0xffffffffu, p, j + 2);
            float p3 = __shfl_sync(0xffffffffu, p, j + 3);
            u64 q0 = pack2(p0, p0), q1 = pack2(p1, p1);
            u64 q2 = pack2(p2, p2), q3 = pack2(p3, p3);
            acc01 = ffma2(h2_to_f32x2((unsigned)w0),         q0, acc01);
            acc23 = ffma2(h2_to_f32x2((unsigned)(w0 >> 32)), q0, acc23);
            acc01 = ffma2(h2_to_f32x2((unsigned)w1),         q1, acc01);
            acc23 = ffma2(h2_to_f32x2((unsigned)(w1 >> 32)), q1, acc23);
            acc01 = ffma2(h2_to_f32x2((unsigned)w2),         q2, acc01);
            acc23 = ffma2(h2_to_f32x2((unsigned)(w2 >> 32)), q2, acc23);
            acc01 = ffma2(h2_to_f32x2((unsigned)w3),         q3, acc01);
            acc23 = ffma2(h2_to_f32x2((unsigned)(w3 >> 32)), q3, acc23);
        }
        for (; j < m; j++) {
            int   s0 = __shfl_sync(0xffffffffu, s, j);
            float p0 = __shfl_sync(0xffffffffu, p, j);
            u64 w0 = *(const u64*)(hb + (size_t)s0 * (D2 * 2));
            u64 q0 = pack2(p0, p0);
            acc01 = ffma2(h2_to_f32x2((unsigned)w0),         q0, acc01);
            acc23 = ffma2(h2_to_f32x2((unsigned)(w0 >> 32)), q0, acc23);
        }
    }
#pragma unroll
    for (int off = 16; off; off >>= 1)
        psum += __shfl_xor_sync(0xffffffffu, psum, off);
    float rs = 1.0f / (psum + 1e-16f);
    float2 v01 = unpack2(acc01);
    float2 v23 = unpack2(acc23);
    float4 bv = *(const float4*)(b2 + 4 * lane);
    float4 o;
    o.x = fmaxf(v01.x * rs + bv.x, 0.f);
    o.y = fmaxf(v01.y * rs + bv.y, 0.f);
    o.z = fmaxf(v23.x * rs + bv.z, 0.f);
    o.w = fmaxf(v23.y * rs + bv.w, 0.f);
    *(float4*)(g_h2act + (size_t)node * D2 + 4 * lane) = o;
}

// ---------------- pool (sorted batch) + end-of-call cleanup ----------------
__global__ void pool_kernel(const int* __restrict__ batch) {
    int t = threadIdx.x;                   // 128 = feature
    int n0 = blockIdx.x * 128;
    int n1 = min(n0 + 128, NN);
    float cur = 0.f;                       // values >= 0 (post-relu)
    int curb = min(max(batch[n0], 0), NG - 1);
    for (int n = n0; n < n1; n++) {
        int b = min(max(batch[n], 0), NG - 1);
        if (b != curb) {
            atomicMax((int*)&g_pool[curb * D2 + t], __float_as_int(cur));
            cur = 0.f;
            curb = b;
        }
        cur = fmaxf(cur, g_h2act[(size_t)n * D2 + t]);
    }
    atomicMax((int*)&g_pool[curb * D2 + t], __float_as_int(cur));
    // cleanup for next call (deg no longer read this call)
    for (int n = n0 + t; n < n1; n += 128) g_deg[n] = 0;
}

__global__ void fc_kernel(const float* __restrict__ fcw,
                          const float* __restrict__ fcb,
                          float* __restrict__ out) {
    int gi = blockIdx.x, t = threadIdx.x;
    __shared__ float gs[D2];
    float gv = g_pool[gi * D2 + t];
    if (!(gv >= 0.f)) gv = 0.f;
    gs[t] = gv;
    __syncthreads();
    float s = 0.f;
    for (int k = 0; k < D2; k++)
        s = fmaf(gs[k], fcw[k * D2 + t], s);
    out[gi * D2 + t] = fmaxf(s + fcb[t], 0.f);
}

// ---------------- launcher ----------------
extern "C" void kernel_launch(void* const* d_in, const int* in_sizes, int n_in,
                              void* d_out, int out_size) {
    const float* x     = (const float*)d_in[0];
    const int*   ei    = (const int*)d_in[1];
    const int*   batch = (const int*)d_in[2];
    const float* W1    = (const float*)d_in[3];
    const float* as1   = (const float*)d_in[4];
    const float* ad1   = (const float*)d_in[5];
    const float* b1    = (const float*)d_in[6];
    const float* W2    = (const float*)d_in[7];
    const float* as2   = (const float*)d_in[8];
    const float* ad2   = (const float*)d_in[9];
    const float* b2    = (const float*)d_in[10];
    const float* fcw   = (const float*)d_in[11];
    const float* fcb   = (const float*)d_in[12];
    float* out = (float*)d_out;

    const int mm2_smem = D1 * MM2_STRIDE * 4;   // ys reuses xs
    static bool attr_set = false;
    if (!attr_set) {
        cudaFuncSetAttribute(mm2_kernel,
                             cudaFuncAttributeMaxDynamicSharedMemorySize,
                             mm2_smem);
        attr_set = true;
    }

    va_kernel<<<3, 256>>>(W1, as1, ad1);                            // idx 0
    mm1_kernel<<<NN / 16, 384>>>(x, W1);                            // idx 1
    convert_kernel<<<(ETOT + 255) / 256, 256>>>(ei);                // idx 2
    scanA_kernel<<<49, 1024>>>();                                   // idx 3 (profiled)
    scanB_kernel<<<1, 64>>>();                                      // idx 4
    scanC_kernel<<<49, 1024>>>();                                   // idx 5
    scatter_kernel<<<(ETOT + 255) / 256, 256>>>();                  // idx 6
    agg1_kernel<<<NN / 4, 128>>>(b1);                               // idx 7

    mm2_kernel<<<(NN + MM2_N - 1) / MM2_N, 128, mm2_smem>>>(W2, as2, ad2);
    agg2_kernel<<<NN / 4, 128>>>(b2);

    pool_kernel<<<(NN + 127) / 128, 128>>>(batch);
    fc_kernel<<<NG, D2>>>(fcw, fcb, out);
}

// round 13
// speedup vs baseline: 1.2997x; 1.0652x over previous
#include <cuda_runtime.h>
#include <cuda_fp16.h>
#include <math.h>

#define NN    50000
#define NE    800000
#define ETOT  850000     // NE + NN self loops
#define H1    10
#define C1    36
#define D1    360        // H1*C1
#define ALP   12         // padded stride for als1/ald1 rows
#define D2    128
#define NG    128

typedef unsigned long long u64;

__device__ __forceinline__ u64 pack2(float a, float b) {
    u64 r; asm("mov.b64 %0, {%1, %2};" : "=l"(r) : "f"(a), "f"(b)); return r;
}
__device__ __forceinline__ u64 ffma2(u64 a, u64 b, u64 c) {
    u64 d; asm("fma.rn.f32x2 %0, %1, %2, %3;" : "=l"(d) : "l"(a), "l"(b), "l"(c)); return d;
}
__device__ __forceinline__ float2 unpack2(u64 v) {
    float2 r; asm("mov.b64 {%0, %1}, %2;" : "=f"(r.x), "=f"(r.y) : "l"(v)); return r;
}
__device__ __forceinline__ u64 h2_to_f32x2(unsigned h2) {
    float2 f = __half22float2(*(__half2*)&h2);
    return pack2(f.x, f.y);
}

// ---------------- device scratch (zero-initialized at module load) ----------------
__device__ int   g_src[ETOT];
__device__ int   g_dst[ETOT];
__device__ int   g_deg[NN];        // zeroed at end of each call (pool_kernel)
__device__ int   g_rowstart[NN];   // becomes row_end after scatter
__device__ int   g_inc[64];        // per-block sums (overwritten each call)
__device__ int   g_ssrc[ETOT];     // src ids in CSR-by-dst order
__device__ float g_va[720];        // folded attention projections [sd][k][h]

__device__ __half g_h1h[(size_t)NN * D1];   // 36 MB (fp16 h1pre)
__device__ float g_als1[NN * ALP];
__device__ float g_ald1[NN * ALP];
__device__ __half g_h1ah[(size_t)NN * D1];  // 36 MB (fp16 h1act)
__device__ __half g_h2h[(size_t)NN * D2];   // 12.8 MB (fp16 h2pre)
__device__ float g_als2[NN];
__device__ float g_ald2[NN];
__device__ float g_h2act[(size_t)NN * D2];  // 25.6 MB
__device__ float g_pool[NG * D2];           // 0-init semantics (values >= 0)

// ---------------- va precompute ----------------
__global__ void va_kernel(const float* __restrict__ W1,
                          const float* __restrict__ as1,
                          const float* __restrict__ ad1) {
    int idx = blockIdx.x * blockDim.x + threadIdx.x;
    if (idx >= 720) return;
    int sd = idx / 360, r = idx % 360;
    int k = r / 10, h = r % 10;
    const float* a = sd ? ad1 : as1;
    float s = 0.f;
    for (int c = 0; c < C1; c++)
        s = fmaf(W1[k * D1 + h * C1 + c], a[h * C1 + c], s);
    g_va[sd * 360 + k * 10 + h] = s;
}

// ---------------- convert edges ----------------
__global__ void convert_kernel(const int* __restrict__ ei) {
    int i = blockIdx.x * blockDim.x + threadIdx.x;
    if (i >= ETOT) return;
    int s, d;
    if (i < NE) {
        s = ei[i]; d = ei[NE + i];
        s = min(max(s, 0), NN - 1);
        d = min(max(d, 0), NN - 1);
    } else {
        s = d = i - NE;                      // self loop
    }
    g_src[i] = s; g_dst[i] = d;
    atomicAdd(&g_deg[d], 1);
}

// ---------------- 3-phase exclusive scan (shuffle-based, no carry chain) ----------
__global__ void scanA_kernel() {
    __shared__ int wsum[32];
    int b = blockIdx.x, t = threadIdx.x;
    int lane = t & 31, wid = t >> 5;
    int i = b * 1024 + t;
    int v = (i < NN) ? g_deg[i] : 0;
    int x = v;
#pragma unroll
    for (int off = 1; off < 32; off <<= 1) {
        int y = __shfl_up_sync(0xffffffffu, x, off);
        if (lane >= off) x += y;
    }
    if (lane == 31) wsum[wid] = x;
    __syncthreads();
    if (wid == 0) {
        int w = wsum[lane];
#pragma unroll
        for (int off = 1; off < 32; off <<= 1) {
            int y = __shfl_up_sync(0xffffffffu, w, off);
            if (lane >= off) w += y;
        }
        wsum[lane] = w;
    }
    __syncthreads();
    int incl = x + (wid ? wsum[wid - 1] : 0);
    if (i < NN) g_rowstart[i] = incl - v;       // exclusive (local)
    if (t == 1023) g_inc[b] = incl;             // block total
}

__global__ void scanB_kernel() {                // 1 block, 64 threads
    int t = threadIdx.x;
    int lane = t & 31, wid = t >> 5;
    __shared__ int w0sum;
    int v = (t < 49) ? g_inc[t] : 0;
    int x = v;
#pragma unroll
    for (int off = 1; off < 32; off <<= 1) {
        int y = __shfl_up_sync(0xffffffffu, x, off);
        if (lane >= off) x += y;
    }
    if (wid == 0 && lane == 31) w0sum = x;
    __syncthreads();
    int incl = x + (wid ? w0sum : 0);
    if (t < 49) g_inc[t] = incl - v;            // exclusive block offsets
}

__global__ void scanC_kernel() {
    int i = blockIdx.x * blockDim.x + threadIdx.x;
    if (i < NN) g_rowstart[i] += g_inc[i >> 10];
}

// ---------------- scatter (rowstart doubles as cursor -> becomes row_end) ---------
__global__ void scatter_kernel() {
    int i = blockIdx.x * blockDim.x + threadIdx.x;
    if (i >= ETOT) return;
    int d = g_dst[i];
    int pos = atomicAdd(&g_rowstart[d], 1);
    g_ssrc[pos] = g_src[i];
}

// ---------------- layer 1 GEMM: [h1h | als | ald] = x @ [W1 | va] ----------------
__global__ void mm1_kernel(const float* __restrict__ x,
                           const float* __restrict__ W1) {
    // 16 nodes per block, 384 threads (one output column each; 360 feat + 20 attn)
    int n0 = blockIdx.x * 16;
    int t = threadIdx.x;
    __shared__ u64 xsp[C1 * 8];   // [k][pair m]
    if (t < 288) {
        int k = t >> 3, m = t & 7;
        float a = x[(size_t)(n0 + 2 * m) * C1 + k];
        float b = x[(size_t)(n0 + 2 * m + 1) * C1 + k];
        xsp[k * 8 + m] = pack2(a, b);
    }
    __syncthreads();
    const float* wptr; int wstride;
    if (t < D1)            { wptr = W1 + t; wstride = D1; }
    else if (t < D1 + 20)  { int j = t - D1; wptr = g_va + (j & 1) * 360 + (j >> 1); wstride = 10; }
    else                   { wptr = W1 + t - 24; wstride = D1; }   // idle lanes, harmless
    u64 acc[8] = {0, 0, 0, 0, 0, 0, 0, 0};
    for (int k = 0; k < C1; k++) {
        float w = wptr[k * wstride];
        u64 ww = pack2(w, w);
        const ulonglong2* row = (const ulonglong2*)(xsp + k * 8);
#pragma unroll
        for (int q = 0; q < 4; q++) {
            ulonglong2 v = row[q];
            acc[2 * q]     = ffma2(v.x, ww, acc[2 * q]);
            acc[2 * q + 1] = ffma2(v.y, ww, acc[2 * q + 1]);
        }
    }
    if (t < D1) {
#pragma unroll
        for (int m = 0; m < 8; m++) {
            float2 v = unpack2(acc[m]);
            g_h1h[(size_t)(n0 + 2 * m) * D1 + t]     = __float2half(v.x);
            g_h1h[(size_t)(n0 + 2 * m + 1) * D1 + t] = __float2half(v.y);
        }
    } else if (t < D1 + 20) {
        int j = t - D1, h = j >> 1;
        float* dst = (j & 1) ? g_ald1 : g_als1;
#pragma unroll
        for (int m = 0; m < 8; m++) {
            float2 v = unpack2(acc[m]);
            dst[(n0 + 2 * m) * ALP + h]     = v.x;
            dst[(n0 + 2 * m + 1) * ALP + h] = v.y;
        }
    }
}

// ---------------- layer-1 aggregation, 4 nodes per block (fp16 in/out) ------------
__global__ void agg1_kernel(const float* __restrict__ b1) {
    int t = threadIdx.x;            // 128
    __shared__ int   ssrcs[128];
    __shared__ float sp[128 * H1];  // 5 KB
    __shared__ float aldn[H1];
    __shared__ float ssum[H1];
    const int head = (t < 90) ? (t / 9) : 0;

    for (int nd = 0; nd < 4; nd++) {
        int node = blockIdx.x * 4 + nd;
        __syncthreads();
        if (t < H1) aldn[t] = g_ald1[node * ALP + t];

        int deg = g_deg[node];
        int start = g_rowstart[node] - deg;   // rowstart holds row_end post-scatter
        u64 acc01 = 0, acc23 = 0;
        float hsum = 0.f;

        for (int base = 0; base < deg; base += 128) {
            int m = min(128, deg - base);
            __syncthreads();
            if (t < m) {
                int s = g_ssrc[start + base + t];
                ssrcs[t] = s;
                const float* ar = &g_als1[(size_t)s * ALP];
                float4 a0 = *(const float4*)ar;
                float4 a1 = *(const float4*)(ar + 4);
                float2 a2 = *(const float2*)(ar + 8);
                float e;
#define DOH(val, h) e = (val) + aldn[h]; e = (e > 0.f) ? e : 0.2f * e; sp[t * H1 + (h)] = __expf(e);
                DOH(a0.x, 0) DOH(a0.y, 1) DOH(a0.z, 2) DOH(a0.w, 3)
                DOH(a1.x, 4) DOH(a1.y, 5) DOH(a1.z, 6) DOH(a1.w, 7)
                DOH(a2.x, 8) DOH(a2.y, 9)
#undef DOH
            }
            __syncthreads();
            if (t < 90) {
                const char* hb = (const char*)g_h1h + 8 * t;  // features 4t..4t+3
                int e = 0;
                for (; e + 2 <= m; e += 2) {
                    int s0 = ssrcs[e], s1 = ssrcs[e + 1];
                    float p0 = sp[e * H1 + head];
                    float p1 = sp[(e + 1) * H1 + head];
                    u64 w0 = *(const u64*)(hb + (size_t)s0 * (D1 * 2));
                    u64 w1 = *(const u64*)(hb + (size_t)s1 * (D1 * 2));
                    u64 q0 = pack2(p0, p0), q1 = pack2(p1, p1);
                    acc01 = ffma2(h2_to_f32x2((unsigned)w0),         q0, acc01);
                    acc23 = ffma2(h2_to_f32x2((unsigned)(w0 >> 32)), q0, acc23);
                    acc01 = ffma2(h2_to_f32x2((unsigned)w1),         q1, acc01);
                    acc23 = ffma2(h2_to_f32x2((unsigned)(w1 >> 32)), q1, acc23);
                }
                if (e < m) {
                    int s0 = ssrcs[e];
                    float p0 = sp[e * H1 + head];
                    u64 w0 = *(const u64*)(hb + (size_t)s0 * (D1 * 2));
                    u64 q0 = pack2(p0, p0);
                    acc01 = ffma2(h2_to_f32x2((unsigned)w0),         q0, acc01);
                    acc23 = ffma2(h2_to_f32x2((unsigned)(w0 >> 32)), q0, acc23);
                }
            } else if (t >= 90 && t < 100) {
                int h = t - 90;
                for (int e = 0; e < m; e++) hsum += sp[e * H1 + h];
            }
        }
        if (t >= 90 && t < 100) ssum[t - 90] = hsum;
        __syncthreads();
        if (t < 90) {
            float rs = 1.0f / (ssum[head] + 1e-16f);
            float2 v01 = unpack2(acc01);
            float2 v23 = unpack2(acc23);
            float4 bv = *(const float4*)(b1 + 4 * t);
            float4 o;
            o.x = v01.x * rs + bv.x;
            o.y = v01.y * rs + bv.y;
            o.z = v23.x * rs + bv.z;
            o.w = v23.y * rs + bv.w;
            o.x = (o.x > 0.f) ? o.x : (__expf(o.x) - 1.f);
            o.y = (o.y > 0.f) ? o.y : (__expf(o.y) - 1.f);
            o.z = (o.z > 0.f) ? o.z : (__expf(o.z) - 1.f);
            o.w = (o.w > 0.f) ? o.w : (__expf(o.w) - 1.f);
            __half2 ha = __floats2half2_rn(o.x, o.y);
            __half2 hbp = __floats2half2_rn(o.z, o.w);
            unsigned ua = *(unsigned*)&ha, ub = *(unsigned*)&hbp;
            *(uint2*)(g_h1ah + (size_t)node * D1 + 4 * t) = make_uint2(ua, ub);
        }
    }
}

// ---------------- layer 2 GEMM + fused al2 (256 threads, node-split halves) -------
#define MM2_N 32
#define MM2_STRIDE 36
#define YS_STRIDE 132
__global__ void mm2_kernel(const float* __restrict__ W2,
                           const float* __restrict__ asrc2,
                           const float* __restrict__ adst2) {
    extern __shared__ float smem_[];
    float* xs = smem_;                          // [D1][36] = 51.8 KB
    int n0 = blockIdx.x * MM2_N;
    int t = threadIdx.x;                        // 256
    int half = t >> 7, col = t & 127;           // half: nodes [half*16, half*16+16)
    for (int i = t; i < MM2_N * (D1 / 2); i += 256) {   // half2 loads
        int n = i / (D1 / 2), kp = i % (D1 / 2), k = 2 * kp;
        float2 f = make_float2(0.f, 0.f);
        if (n0 + n < NN)
            f = __half22float2(*(const __half2*)(g_h1ah + (size_t)(n0 + n) * D1 + k));
        xs[k * MM2_STRIDE + n] = f.x;
        xs[(k + 1) * MM2_STRIDE + n] = f.y;
    }
    __syncthreads();
    u64 acc[8];                                 // 16 nodes (8 pairs)
#pragma unroll
    for (int p = 0; p < 8; p++) acc[p] = 0;
    for (int k = 0; k < D1; k++) {
        float w = W2[k * D2 + col];
        u64 wf2 = pack2(w, w);
        const ulonglong2* row = (const ulonglong2*)(xs + k * MM2_STRIDE + half * 16);
#pragma unroll
        for (int q = 0; q < 4; q++) {
            ulonglong2 v = row[q];
            acc[2 * q]     = ffma2(v.x, wf2, acc[2 * q]);
            acc[2 * q + 1] = ffma2(v.y, wf2, acc[2 * q + 1]);
        }
    }
    __syncthreads();                 // xs no longer needed; reuse as ys
    float* ys = smem_;               // [32][132] = 16.9 KB
#pragma unroll
    for (int p = 0; p < 8; p++) {
        float2 a = unpack2(acc[p]);
        int nl = half * 16 + 2 * p;
        int n = n0 + nl;
        if (n < NN)     g_h2h[(size_t)n * D2 + col] = __float2half(a.x);
        if (n + 1 < NN) g_h2h[(size_t)(n + 1) * D2 + col] = __float2half(a.y);
        ys[nl * YS_STRIDE + col]       = a.x;
        ys[(nl + 1) * YS_STRIDE + col] = a.y;
    }
    __syncthreads();
    {
        int n = t >> 3, c0 = (t & 7) * 16;      // 8 threads per node, 16 feats each
        float ss = 0.f, sd = 0.f;
        const float* yr = ys + n * YS_STRIDE;
        for (int k = c0; k < c0 + 16; k++) {
            float v = yr[k];
            ss = fmaf(v, asrc2[k], ss);
            sd = fmaf(v, adst2[k], sd);
        }
        ss += __shfl_xor_sync(0xffffffffu, ss, 1);
        ss += __shfl_xor_sync(0xffffffffu, ss, 2);
        ss += __shfl_xor_sync(0xffffffffu, ss, 4);
        sd += __shfl_xor_sync(0xffffffffu, sd, 1);
        sd += __shfl_xor_sync(0xffffffffu, sd, 2);
        sd += __shfl_xor_sync(0xffffffffu, sd, 4);
        if ((t & 7) == 0 && n0 + n < NN) {
            g_als2[n0 + n] = ss;
            g_ald2[n0 + n] = sd;
        }
    }
}

// ---------------- layer-2 aggregation: warp per node (fp16 gather) ----------------
__global__ void agg2_kernel(const float* __restrict__ b2) {
    int node = blockIdx.x * 4 + (threadIdx.x >> 5);
    int lane = threadIdx.x & 31;
    float aldn = g_ald2[node];
    int deg = g_deg[node];
    int start = g_rowstart[node] - deg;
    u64 acc01 = 0, acc23 = 0;
    float psum = 0.f;
    const char* hb = (const char*)g_h2h + 8 * lane;   // features 4*lane..4*lane+3
    for (int base = 0; base < deg; base += 32) {
        int m = min(32, deg - base);
        int s = 0; float p = 0.f;
        if (lane < m) {
            s = g_ssrc[start + base + lane];
            float e = g_als2[s] + aldn;
            e = (e > 0.f) ? e : 0.2f * e;
            p = __expf(e);
        }
        psum += p;
        int j = 0;
        for (; j + 4 <= m; j += 4) {
            int   s0 = __shfl_sync(0xffffffffu, s, j);
            int   s1 = __shfl_sync(0xffffffffu, s, j + 1);
            int   s2 = __shfl_sync(0xffffffffu, s, j + 2);
            int   s3 = __shfl_sync(0xffffffffu, s, j + 3);
            u64 w0 = *(const u64*)(hb + (size_t)s0 * (D2 * 2));
            u64 w1 = *(const u64*)(hb + (size_t)s1 * (D2 * 2));
            u64 w2 = *(const u64*)(hb + (size_t)s2 * (D2 * 2));
            u64 w3 = *(const u64*)(hb + (size_t)s3 * (D2 * 2));
            float p0 = __shfl_sync(0xffffffffu, p, j);
            float p1 = __shfl_sync(0xffffffffu, p, j + 1);
            float p2 = __shfl_sync(0xffffffffu, p, j + 2);
            float p3 = __shfl_sync(0xffffffffu, p, j + 3);
            u64 q0 = pack2(p0, p0), q1 = pack2(p1, p1);
            u64 q2 = pack2(p2, p2), q3 = pack2(p3, p3);
            acc01 = ffma2(h2_to_f32x2((unsigned)w0),         q0, acc01);
            acc23 = ffma2(h2_to_f32x2((unsigned)(w0 >> 32)), q0, acc23);
            acc01 = ffma2(h2_to_f32x2((unsigned)w1),         q1, acc01);
            acc23 = ffma2(h2_to_f32x2((unsigned)(w1 >> 32)), q1, acc23);
            acc01 = ffma2(h2_to_f32x2((unsigned)w2),         q2, acc01);
            acc23 = ffma2(h2_to_f32x2((unsigned)(w2 >> 32)), q2, acc23);
            acc01 = ffma2(h2_to_f32x2((unsigned)w3),         q3, acc01);
            acc23 = ffma2(h2_to_f32x2((unsigned)(w3 >> 32)), q3, acc23);
        }
        for (; j < m; j++) {
            int   s0 = __shfl_sync(0xffffffffu, s, j);
            float p0 = __shfl_sync(0xffffffffu, p, j);
            u64 w0 = *(const u64*)(hb + (size_t)s0 * (D2 * 2));
            u64 q0 = pack2(p0, p0);
            acc01 = ffma2(h2_to_f32x2((unsigned)w0),         q0, acc01);
            acc23 = ffma2(h2_to_f32x2((unsigned)(w0 >> 32)), q0, acc23);
        }
    }
#pragma unroll
    for (int off = 16; off; off >>= 1)
        psum += __shfl_xor_sync(0xffffffffu, psum, off);
    float rs = 1.0f / (psum + 1e-16f);
    float2 v01 = unpack2(acc01);
    float2 v23 = unpack2(acc23);
    float4 bv = *(const float4*)(b2 + 4 * lane);
    float4 o;
    o.x = fmaxf(v01.x * rs + bv.x, 0.f);
    o.y = fmaxf(v01.y * rs + bv.y, 0.f);
    o.z = fmaxf(v23.x * rs + bv.z, 0.f);
    o.w = fmaxf(v23.y * rs + bv.w, 0.f);
    *(float4*)(g_h2act + (size_t)node * D2 + 4 * lane) = o;
}

// ---------------- pool (sorted batch) + end-of-call cleanup ----------------
__global__ void pool_kernel(const int* __restrict__ batch) {
    int t = threadIdx.x;                   // 128 = feature
    int n0 = blockIdx.x * 128;
    int n1 = min(n0 + 128, NN);
    float cur = 0.f;                       // values >= 0 (post-relu)
    int curb = min(max(batch[n0], 0), NG - 1);
    for (int n = n0; n < n1; n++) {
        int b = min(max(batch[n], 0), NG - 1);
        if (b != curb) {
            atomicMax((int*)&g_pool[curb * D2 + t], __float_as_int(cur));
            cur = 0.f;
            curb = b;
        }
        cur = fmaxf(cur, g_h2act[(size_t)n * D2 + t]);
    }
    atomicMax((int*)&g_pool[curb * D2 + t], __float_as_int(cur));
    // cleanup for next call (deg no longer read this call)
    for (int n = n0 + t; n < n1; n += 128) g_deg[n] = 0;
}

__global__ void fc_kernel(const float* __restrict__ fcw,
                          const float* __restrict__ fcb,
                          float* __restrict__ out) {
    int gi = blockIdx.x, t = threadIdx.x;
    __shared__ float gs[D2];
    float gv = g_pool[gi * D2 + t];
    if (!(gv >= 0.f)) gv = 0.f;
    gs[t] = gv;
    __syncthreads();
    float s = 0.f;
    for (int k = 0; k < D2; k++)
        s = fmaf(gs[k], fcw[k * D2 + t], s);
    out[gi * D2 + t] = fmaxf(s + fcb[t], 0.f);
}

// ---------------- launcher ----------------
extern "C" void kernel_launch(void* const* d_in, const int* in_sizes, int n_in,
                              void* d_out, int out_size) {
    const float* x     = (const float*)d_in[0];
    const int*   ei    = (const int*)d_in[1];
    const int*   batch = (const int*)d_in[2];
    const float* W1    = (const float*)d_in[3];
    const float* as1   = (const float*)d_in[4];
    const float* ad1   = (const float*)d_in[5];
    const float* b1    = (const float*)d_in[6];
    const float* W2    = (const float*)d_in[7];
    const float* as2   = (const float*)d_in[8];
    const float* ad2   = (const float*)d_in[9];
    const float* b2    = (const float*)d_in[10];
    const float* fcw   = (const float*)d_in[11];
    const float* fcb   = (const float*)d_in[12];
    float* out = (float*)d_out;

    const int mm2_smem = D1 * MM2_STRIDE * 4;   // ys reuses xs
    static bool attr_set = false;
    if (!attr_set) {
        cudaFuncSetAttribute(mm2_kernel,
                             cudaFuncAttributeMaxDynamicSharedMemorySize,
                             mm2_smem);
        attr_set = true;
    }

    va_kernel<<<3, 256>>>(W1, as1, ad1);                            // idx 0
    mm1_kernel<<<NN / 16, 384>>>(x, W1);                            // idx 1
    convert_kernel<<<(ETOT + 255) / 256, 256>>>(ei);                // idx 2
    scanA_kernel<<<49, 1024>>>();                                   // idx 3 (profiled)
    scanB_kernel<<<1, 64>>>();                                      // idx 4
    scanC_kernel<<<49, 1024>>>();                                   // idx 5
    scatter_kernel<<<(ETOT + 255) / 256, 256>>>();                  // idx 6
    agg1_kernel<<<NN / 4, 128>>>(b1);                               // idx 7

    mm2_kernel<<<(NN + MM2_N - 1) / MM2_N, 256, mm2_smem>>>(W2, as2, ad2);
    agg2_kernel<<<NN / 4, 128>>>(b2);

    pool_kernel<<<(NN + 127) / 128, 128>>>(batch);
    fc_kernel<<<NG, D2>>>(fcw, fcb, out);
}